// round 6
// baseline (speedup 1.0000x reference)
#include <cuda_runtime.h>
#include <stdint.h>
#include <math.h>

#define BB 16
#define CC 3
#define HW 50176             // 224*224
#define EMBN 16
#define NSEG 196
#define MCN 16
#define NTOT (BB*NSEG*MCN)   // 50176
#define RR 15                // rank of gemb
#define NPK 120              // packed 15x15 lower triangle
#define BLK 14               // rows per Gram snapshot block (196/14)

#define SZ_MASK (BB*CC*HW*MCN)
#define OFF_GP  (SZ_MASK)
#define OFF_PP  (OFF_GP + BB*NSEG)
#define OFF_SIG (OFF_PP + BB*HW)

// -------------------- device scratch --------------------
__device__ float g_sums[BB*NSEG*17];
__device__ float g_mu[BB*NSEG];
__device__ float g_gemb[BB*NSEG*16];
__device__ float g_eps[NTOT];
__device__ float g_logi[NTOT];
__device__ float g_hard[NTOT];

// -------------------- threefry2x32 --------------------
__host__ __device__ inline void tf2x32(uint32_t k0, uint32_t k1,
                                       uint32_t x0, uint32_t x1,
                                       uint32_t& o0, uint32_t& o1) {
    uint32_t ks2 = k0 ^ k1 ^ 0x1BD11BDAu;
    x0 += k0; x1 += k1;
#define TF_RND(r) { x0 += x1; x1 = (x1 << (r)) | (x1 >> (32 - (r))); x1 ^= x0; }
    TF_RND(13) TF_RND(15) TF_RND(26) TF_RND(6)
    x0 += k1;  x1 += ks2 + 1u;
    TF_RND(17) TF_RND(29) TF_RND(16) TF_RND(24)
    x0 += ks2; x1 += k0 + 2u;
    TF_RND(13) TF_RND(15) TF_RND(26) TF_RND(6)
    x0 += k0;  x1 += k1 + 3u;
    TF_RND(17) TF_RND(29) TF_RND(16) TF_RND(24)
    x0 += k1;  x1 += ks2 + 4u;
    TF_RND(13) TF_RND(15) TF_RND(26) TF_RND(6)
    x0 += ks2; x1 += k0 + 5u;
#undef TF_RND
    o0 = x0; o1 = x1;
}

__device__ __forceinline__ float erfinv_xla(float x) {
    float w = -log1pf(-x * x);
    float p;
    if (w < 5.0f) {
        w = w - 2.5f;
        p =               2.81022636e-08f;
        p = fmaf(p, w,    3.43273939e-07f);
        p = fmaf(p, w,   -3.5233877e-06f);
        p = fmaf(p, w,   -4.39150654e-06f);
        p = fmaf(p, w,    0.00021858087f);
        p = fmaf(p, w,   -0.00125372503f);
        p = fmaf(p, w,   -0.00417768164f);
        p = fmaf(p, w,    0.246640727f);
        p = fmaf(p, w,    1.50140941f);
    } else {
        w = sqrtf(w) - 3.0f;
        p =              -0.000200214257f;
        p = fmaf(p, w,    0.000100950558f);
        p = fmaf(p, w,    0.00134934322f);
        p = fmaf(p, w,   -0.00367342844f);
        p = fmaf(p, w,    0.00573950773f);
        p = fmaf(p, w,   -0.0076224613f);
        p = fmaf(p, w,    0.00943887047f);
        p = fmaf(p, w,    1.00167406f);
        p = fmaf(p, w,    2.83297682f);
    }
    return p * x;
}

// -------------------- kernel 1: conv + pixel_probs + segment sums --------------------
__global__ void k_emb_sums(const float* __restrict__ x, const int* __restrict__ groups,
                           const float* __restrict__ Wc, const float* __restrict__ bc,
                           float* __restrict__ out_pp) {
    __shared__ float sW[EMBN*CC];
    __shared__ float sB[EMBN];
    __shared__ float acc[NSEG*17];
    const int tid = threadIdx.x;
    const int b   = blockIdx.y;
    if (tid < EMBN*CC) sW[tid] = Wc[tid];
    if (tid < EMBN)    sB[tid] = bc[tid];
    for (int i = tid; i < NSEG*17; i += blockDim.x) acc[i] = 0.0f;
    __syncthreads();

    const int chunk = HW / gridDim.x;
    const int p0 = blockIdx.x * chunk;
    const float* xb = x + (size_t)b * CC * HW;
    for (int p = p0 + tid; p < p0 + chunk; p += blockDim.x) {
        float x0 = xb[p], x1 = xb[HW + p], x2 = xb[2*HW + p];
        int g = groups[b*HW + p];
        float* a = acc + g * 17;
#pragma unroll
        for (int e = 0; e < EMBN; ++e) {
            float s = fmaf(x2, sW[e*3+2], fmaf(x1, sW[e*3+1], x0 * sW[e*3]));
            float v = s + sB[e];
            if (e == 0) out_pp[b*HW + p] = 1.0f / (1.0f + expf(-v));
            atomicAdd(&a[e], v);
        }
        atomicAdd(&a[16], 1.0f);
    }
    __syncthreads();
    float* gs = g_sums + b * NSEG * 17;
    for (int i = tid; i < NSEG*17; i += blockDim.x) atomicAdd(&gs[i], acc[i]);
}

// -------------------- kernel 2: means --------------------
__global__ void k_means(float* __restrict__ out_gp) {
    int t = blockIdx.x * blockDim.x + threadIdx.x;
    if (t >= BB*NSEG) return;
    const float* s = g_sums + t * 17;
    float cm = fmaxf(s[16], 1.0f);
    float a0 = s[0] / cm;
    g_mu[t] = a0;
    out_gp[t] = 1.0f / (1.0f + expf(-a0));
    float* ge = g_gemb + t * 16;
#pragma unroll
    for (int e = 1; e < 16; ++e) ge[e-1] = s[e] / cm;
    ge[15] = 0.0f;
}

// -------------------- kernel 3: sigma --------------------
__global__ void k_sigma(float* __restrict__ out_sig) {
    const int sRow = blockIdx.x, b = blockIdx.y;
    __shared__ float gs[16];
    int t = threadIdx.x;
    if (t < 16) gs[t] = g_gemb[(b*NSEG + sRow)*16 + t];
    __syncthreads();
    if (t >= NSEG) return;
    const float4* gt = (const float4*)(g_gemb + (size_t)(b*NSEG + t)*16);
    float4 a0 = gt[0], a1 = gt[1], a2 = gt[2], a3 = gt[3];
    float d = gs[0]*a0.x;
    d = fmaf(gs[1],  a0.y, d); d = fmaf(gs[2],  a0.z, d); d = fmaf(gs[3],  a0.w, d);
    d = fmaf(gs[4],  a1.x, d); d = fmaf(gs[5],  a1.y, d); d = fmaf(gs[6],  a1.z, d);
    d = fmaf(gs[7],  a1.w, d); d = fmaf(gs[8],  a2.x, d); d = fmaf(gs[9],  a2.y, d);
    d = fmaf(gs[10], a2.z, d); d = fmaf(gs[11], a2.w, d); d = fmaf(gs[12], a3.x, d);
    d = fmaf(gs[13], a3.y, d); d = fmaf(gs[14], a3.z, d);
    if (t == sRow) d += 0.001f;
    out_sig[(size_t)(b*NSEG + sRow)*NSEG + t] = d;
}

// -------------------- kernel 4: RNG --------------------
__global__ void k_rng(uint32_t g0, uint32_t g1, uint32_t u0, uint32_t u1) {
    int i = blockIdx.x * blockDim.x + threadIdx.x;
    if (i >= NTOT) return;
    uint32_t a0, a1;
    tf2x32(g0, g1, 0u, (uint32_t)i, a0, a1);
    {
        uint32_t bits = a0 ^ a1;
        float f  = __uint_as_float((bits >> 9) | 0x3f800000u) - 1.0f;
        const float lo = __uint_as_float(0xBF7FFFFFu);
        const float d  = __fadd_rn(1.0f, -lo);
        float u  = fmaxf(lo, __fadd_rn(__fmul_rn(f, d), lo));
        g_eps[i] = __uint_as_float(0x3FB504F3u) * erfinv_xla(u);
    }
    tf2x32(u0, u1, 0u, (uint32_t)i, a0, a1);
    {
        uint32_t bits = a0 ^ a1;
        float f  = __uint_as_float((bits >> 9) | 0x3f800000u) - 1.0f;
        const float lo = 1e-6f;
        const float hi = (float)(1.0 - 1e-6);
        const float d  = __fadd_rn(hi, -lo);
        float u  = fmaxf(lo, __fadd_rn(__fmul_rn(f, d), lo));
        g_logi[i] = logf(u) - log1pf(-u);
    }
}

// -------------------- kernel 5: low-rank Cholesky + logits + hard bits --------------------
// sigma = U U^T + s2*I with U = gemb (196 x 15).
// v_i = (I + U_{<i}^T U_{<i}/s2)^{-1} u_i   (196 independent 15x15 SPD solves)
// d_i = s2 + u_i.v_i ; L_ii = sqrt(d_i); L_ji = u_j.v_i/sqrt(d_i)
// (L eps)_j = u_j.S_{j-1} + sqrt(d_j) eps_j,  S_j = sum_{i<=j} (eps_i/sqrt(d_i)) v_i
__global__ __launch_bounds__(256, 1) void k_lr() {
    __shared__ float su[NSEG][16];         // U rows
    __shared__ float sv[NSEG][16];         // v rows
    __shared__ float sg[NSEG/BLK][NPK];    // Gram snapshots (before each block)
    __shared__ float ssd[NSEG], sisd[NSEG];
    const int b = blockIdx.x, tid = threadIdx.x;
    const float s2 = 0.001f;
    const float inv_s2 = 1.0f / s2;

    // load U
    for (int i = tid; i < NSEG*16; i += 256) {
        int r = i >> 4, c = i & 15;
        su[r][c] = (c < RR) ? g_gemb[(b*NSEG + r)*16 + c] : 0.0f;
    }
    __syncthreads();

    // Gram prefix snapshots: sg[blk][e] = sum_{l < blk*BLK} u_l[j]*u_l[k]
    if (tid < NPK) {
        int e = tid, j = 0;
        while ((j+1)*(j+2)/2 <= e) ++j;
        int k = e - j*(j+1)/2;
        float accg = 0.0f;
        for (int blk = 0; blk < NSEG/BLK; ++blk) {
            sg[blk][e] = accg;
            int l0 = blk*BLK;
#pragma unroll
            for (int l = 0; l < BLK; ++l)
                accg = fmaf(su[l0+l][j], su[l0+l][k], accg);
        }
    }
    __syncthreads();

    // per-row independent solve (one thread per row)
    if (tid < NSEG) {
        const int i = tid, blk = i / BLK;
        float Bm[NPK];
        for (int e = 0; e < NPK; ++e) Bm[e] = sg[blk][e];
        for (int l = blk*BLK; l < i; ++l) {
            int e = 0;
            for (int j = 0; j < RR; ++j) {
                float ulj = su[l][j];
                for (int k = 0; k <= j; ++k, ++e)
                    Bm[e] = fmaf(ulj, su[l][k], Bm[e]);
            }
        }
        // M = I + B/s2 (packed lower)
        {
            int e = 0;
            for (int j = 0; j < RR; ++j)
                for (int k = 0; k <= j; ++k, ++e)
                    Bm[e] = (j == k) ? fmaf(Bm[e], inv_s2, 1.0f) : Bm[e]*inv_s2;
        }
        // in-place packed Cholesky of M (no unroll: keep compile light)
        for (int k = 0; k < RR; ++k) {
            int kk = k*(k+1)/2 + k;
            float dk = sqrtf(Bm[kk]);
            Bm[kk] = dk;
            float inv = 1.0f / dk;
            for (int j = k+1; j < RR; ++j) Bm[j*(j+1)/2 + k] *= inv;
            for (int j = k+1; j < RR; ++j) {
                float ljk = Bm[j*(j+1)/2 + k];
                for (int l = k+1; l <= j; ++l)
                    Bm[j*(j+1)/2 + l] = fmaf(-ljk, Bm[l*(l+1)/2 + k], Bm[j*(j+1)/2 + l]);
            }
        }
        // forward solve L y = u_i
        float y[RR];
        for (int j = 0; j < RR; ++j) {
            float s = su[i][j];
            for (int k = 0; k < j; ++k) s = fmaf(-Bm[j*(j+1)/2 + k], y[k], s);
            y[j] = s / Bm[j*(j+1)/2 + j];
        }
        // back solve L^T v = y
        float v[RR];
        for (int j = RR-1; j >= 0; --j) {
            float s = y[j];
            for (int k = j+1; k < RR; ++k) s = fmaf(-Bm[k*(k+1)/2 + j], v[k], s);
            v[j] = s / Bm[j*(j+1)/2 + j];
        }
        float d = s2;
        for (int c = 0; c < RR; ++c) { d = fmaf(su[i][c], v[c], d); sv[i][c] = v[c]; }
        sv[i][15] = 0.0f;
        float sd = sqrtf(d);
        ssd[i] = sd;
        sisd[i] = 1.0f / sd;
    }
    __syncthreads();

    // phase B: prefix over rows, one thread per MC column
    if (tid < MCN) {
        const int m = tid;
        float S[RR];
#pragma unroll
        for (int c = 0; c < RR; ++c) S[c] = 0.0f;
        for (int j = 0; j < NSEG; ++j) {
            int gi = (b*NSEG + j)*MCN + m;
            float ej = g_eps[gi];
            float lg = g_logi[gi];
            float dot = 0.0f;
#pragma unroll
            for (int c = 0; c < RR; ++c) dot = fmaf(su[j][c], S[c], dot);
            float z = g_mu[b*NSEG + j] + dot + ssd[j]*ej + lg;
            float r = 1.0f / (1.0f + expf(-z));
            g_hard[gi] = (r > 0.5f) ? 1.0f : 0.0f;
            float w = ej * sisd[j];
#pragma unroll
            for (int c = 0; c < RR; ++c) S[c] = fmaf(w, sv[j][c], S[c]);
        }
    }
}

// -------------------- kernel 6: gather mask --------------------
__global__ void k_mask(const int* __restrict__ groups, float* __restrict__ mask) {
    const int idx = blockIdx.x * blockDim.x + threadIdx.x;
    const int c = blockIdx.y, b = blockIdx.z;
    const int p = idx >> 2, j = idx & 3;
    const int g = __ldg(&groups[b*HW + p]);
    float4 v = ((const float4*)g_hard)[(b*NSEG + g)*4 + j];
    ((float4*)mask)[ (size_t)((b*CC + c)*HW + p)*4 + j ] = v;
}

// -------------------- launch --------------------
extern "C" void kernel_launch(void* const* d_in, const int* in_sizes, int n_in,
                              void* d_out, int out_size) {
    (void)in_sizes; (void)n_in; (void)out_size;
    const float* x      = (const float*)d_in[0];
    const int*   groups = (const int*)d_in[1];
    const float* Wc     = (const float*)d_in[2];
    const float* bc     = (const float*)d_in[3];
    float* out      = (float*)d_out;
    float* out_mask = out;
    float* out_gp   = out + OFF_GP;
    float* out_pp   = out + OFF_PP;
    float* out_sig  = out + OFF_SIG;

    void* sumsPtr = nullptr;
    cudaGetSymbolAddress(&sumsPtr, g_sums);
    cudaMemsetAsync(sumsPtr, 0, sizeof(float)*BB*NSEG*17);

    uint32_t kg0, kg1, ku0, ku1;
    tf2x32(0u, 42u, 0u, 0u, kg0, kg1);
    tf2x32(0u, 42u, 0u, 1u, ku0, ku1);
    k_rng<<<(NTOT + 255)/256, 256>>>(kg0, kg1, ku0, ku1);

    k_emb_sums<<<dim3(8, BB), 256>>>(x, groups, Wc, bc, out_pp);
    k_means<<<(BB*NSEG + 255)/256, 256>>>(out_gp);
    k_sigma<<<dim3(NSEG, BB), 256>>>(out_sig);
    k_lr<<<BB, 256>>>();
    k_mask<<<dim3(HW*4/256, CC, BB), 256>>>(groups, out_mask);
}

// round 8
// speedup vs baseline: 2.4129x; 2.4129x over previous
#include <cuda_runtime.h>
#include <stdint.h>
#include <math.h>

#define BB 16
#define CC 3
#define HW 50176             // 224*224
#define EMBN 16
#define NSEG 196
#define MCN 16
#define NTOT (BB*NSEG*MCN)   // 50176
#define RR 15                // rank of gemb
#define NPK 120              // packed 15x15 lower triangle
#define BLKA 7               // rows per Gram snapshot block
#define NSNAP (NSEG/BLKA)    // 28
#define CH 14                // scan chunk size
#define NCH (NSEG/CH)        // 14

#define SZ_MASK (BB*CC*HW*MCN)
#define OFF_GP  (SZ_MASK)
#define OFF_PP  (OFF_GP + BB*NSEG)
#define OFF_SIG (OFF_PP + BB*HW)

// -------------------- device scratch --------------------
__device__ float g_sums[BB*NSEG*17];
__device__ float g_mu[BB*NSEG];
__device__ float g_gemb[BB*NSEG*16];
__device__ float g_eps[NTOT];
__device__ float g_logi[NTOT];
__device__ float g_hard[NTOT];

// -------------------- threefry2x32 --------------------
__host__ __device__ inline void tf2x32(uint32_t k0, uint32_t k1,
                                       uint32_t x0, uint32_t x1,
                                       uint32_t& o0, uint32_t& o1) {
    uint32_t ks2 = k0 ^ k1 ^ 0x1BD11BDAu;
    x0 += k0; x1 += k1;
#define TF_RND(r) { x0 += x1; x1 = (x1 << (r)) | (x1 >> (32 - (r))); x1 ^= x0; }
    TF_RND(13) TF_RND(15) TF_RND(26) TF_RND(6)
    x0 += k1;  x1 += ks2 + 1u;
    TF_RND(17) TF_RND(29) TF_RND(16) TF_RND(24)
    x0 += ks2; x1 += k0 + 2u;
    TF_RND(13) TF_RND(15) TF_RND(26) TF_RND(6)
    x0 += k0;  x1 += k1 + 3u;
    TF_RND(17) TF_RND(29) TF_RND(16) TF_RND(24)
    x0 += k1;  x1 += ks2 + 4u;
    TF_RND(13) TF_RND(15) TF_RND(26) TF_RND(6)
    x0 += ks2; x1 += k0 + 5u;
#undef TF_RND
    o0 = x0; o1 = x1;
}

__device__ __forceinline__ float erfinv_xla(float x) {
    float w = -log1pf(-x * x);
    float p;
    if (w < 5.0f) {
        w = w - 2.5f;
        p =               2.81022636e-08f;
        p = fmaf(p, w,    3.43273939e-07f);
        p = fmaf(p, w,   -3.5233877e-06f);
        p = fmaf(p, w,   -4.39150654e-06f);
        p = fmaf(p, w,    0.00021858087f);
        p = fmaf(p, w,   -0.00125372503f);
        p = fmaf(p, w,   -0.00417768164f);
        p = fmaf(p, w,    0.246640727f);
        p = fmaf(p, w,    1.50140941f);
    } else {
        w = sqrtf(w) - 3.0f;
        p =              -0.000200214257f;
        p = fmaf(p, w,    0.000100950558f);
        p = fmaf(p, w,    0.00134934322f);
        p = fmaf(p, w,   -0.00367342844f);
        p = fmaf(p, w,    0.00573950773f);
        p = fmaf(p, w,   -0.0076224613f);
        p = fmaf(p, w,    0.00943887047f);
        p = fmaf(p, w,    1.00167406f);
        p = fmaf(p, w,    2.83297682f);
    }
    return p * x;
}

// -------------------- kernel 1: conv + pixel_probs + segment sums --------------------
__global__ void k_emb_sums(const float* __restrict__ x, const int* __restrict__ groups,
                           const float* __restrict__ Wc, const float* __restrict__ bc,
                           float* __restrict__ out_pp) {
    __shared__ float sW[EMBN*CC];
    __shared__ float sB[EMBN];
    __shared__ float acc[NSEG*17];
    const int tid = threadIdx.x;
    const int b   = blockIdx.y;
    if (tid < EMBN*CC) sW[tid] = Wc[tid];
    if (tid < EMBN)    sB[tid] = bc[tid];
    for (int i = tid; i < NSEG*17; i += blockDim.x) acc[i] = 0.0f;
    __syncthreads();

    const int chunk = HW / gridDim.x;
    const int p0 = blockIdx.x * chunk;
    const float* xb = x + (size_t)b * CC * HW;
    for (int p = p0 + tid; p < p0 + chunk; p += blockDim.x) {
        float x0 = xb[p], x1 = xb[HW + p], x2 = xb[2*HW + p];
        int g = groups[b*HW + p];
        float* a = acc + g * 17;
#pragma unroll
        for (int e = 0; e < EMBN; ++e) {
            float s = fmaf(x2, sW[e*3+2], fmaf(x1, sW[e*3+1], x0 * sW[e*3]));
            float v = s + sB[e];
            if (e == 0) out_pp[b*HW + p] = 1.0f / (1.0f + expf(-v));
            atomicAdd(&a[e], v);
        }
        atomicAdd(&a[16], 1.0f);
    }
    __syncthreads();
    float* gs = g_sums + b * NSEG * 17;
    for (int i = tid; i < NSEG*17; i += blockDim.x) atomicAdd(&gs[i], acc[i]);
}

// -------------------- kernel 2: means --------------------
__global__ void k_means(float* __restrict__ out_gp) {
    int t = blockIdx.x * blockDim.x + threadIdx.x;
    if (t >= BB*NSEG) return;
    const float* s = g_sums + t * 17;
    float cm = fmaxf(s[16], 1.0f);
    float a0 = s[0] / cm;
    g_mu[t] = a0;
    out_gp[t] = 1.0f / (1.0f + expf(-a0));
    float* ge = g_gemb + t * 16;
#pragma unroll
    for (int e = 1; e < 16; ++e) ge[e-1] = s[e] / cm;
    ge[15] = 0.0f;
}

// -------------------- kernel 3: sigma --------------------
__global__ void k_sigma(float* __restrict__ out_sig) {
    const int sRow = blockIdx.x, b = blockIdx.y;
    __shared__ float gs[16];
    int t = threadIdx.x;
    if (t < 16) gs[t] = g_gemb[(b*NSEG + sRow)*16 + t];
    __syncthreads();
    if (t >= NSEG) return;
    const float4* gt = (const float4*)(g_gemb + (size_t)(b*NSEG + t)*16);
    float4 a0 = gt[0], a1 = gt[1], a2 = gt[2], a3 = gt[3];
    float d = gs[0]*a0.x;
    d = fmaf(gs[1],  a0.y, d); d = fmaf(gs[2],  a0.z, d); d = fmaf(gs[3],  a0.w, d);
    d = fmaf(gs[4],  a1.x, d); d = fmaf(gs[5],  a1.y, d); d = fmaf(gs[6],  a1.z, d);
    d = fmaf(gs[7],  a1.w, d); d = fmaf(gs[8],  a2.x, d); d = fmaf(gs[9],  a2.y, d);
    d = fmaf(gs[10], a2.z, d); d = fmaf(gs[11], a2.w, d); d = fmaf(gs[12], a3.x, d);
    d = fmaf(gs[13], a3.y, d); d = fmaf(gs[14], a3.z, d);
    if (t == sRow) d += 0.001f;
    out_sig[(size_t)(b*NSEG + sRow)*NSEG + t] = d;
}

// -------------------- kernel 4: RNG --------------------
__global__ void k_rng(uint32_t g0, uint32_t g1, uint32_t u0, uint32_t u1) {
    int i = blockIdx.x * blockDim.x + threadIdx.x;
    if (i >= NTOT) return;
    uint32_t a0, a1;
    tf2x32(g0, g1, 0u, (uint32_t)i, a0, a1);
    {
        uint32_t bits = a0 ^ a1;
        float f  = __uint_as_float((bits >> 9) | 0x3f800000u) - 1.0f;
        const float lo = __uint_as_float(0xBF7FFFFFu);
        const float d  = __fadd_rn(1.0f, -lo);
        float u  = fmaxf(lo, __fadd_rn(__fmul_rn(f, d), lo));
        g_eps[i] = __uint_as_float(0x3FB504F3u) * erfinv_xla(u);
    }
    tf2x32(u0, u1, 0u, (uint32_t)i, a0, a1);
    {
        uint32_t bits = a0 ^ a1;
        float f  = __uint_as_float((bits >> 9) | 0x3f800000u) - 1.0f;
        const float lo = 1e-6f;
        const float hi = (float)(1.0 - 1e-6);
        const float d  = __fadd_rn(hi, -lo);
        float u  = fmaxf(lo, __fadd_rn(__fmul_rn(f, d), lo));
        g_logi[i] = logf(u) - log1pf(-u);
    }
}

// -------------------- kernel 5: low-rank Cholesky + logits + hard bits --------------------
// sigma = U U^T + s2*I with U = gemb (196 x 15).
// v_i = (I + U_{<i}^T U_{<i}/s2)^{-1} u_i   (196 independent 15x15 SPD solves, registers)
// d_i = s2 + u_i.v_i ; (L eps)_j = u_j.S_{j-1} + sqrt(d_j) eps_j,
// S_j = sum_{i<=j} (eps_i/sqrt(d_i)) v_i   (computed with a 3-phase chunked scan)
__global__ __launch_bounds__(256) void k_lr() {
    __shared__ float su[NSEG][17];     // U rows (stride 17: bank-conflict-free column reads)
    __shared__ float sv[NSEG][17];     // v rows
    __shared__ float sbuf[3584];       // phase A: Gram snapshots [28][120]; phase B: T[14][16][16]
    __shared__ float ssd[NSEG], sisd[NSEG];
    const int b = blockIdx.x, tid = threadIdx.x;
    const float s2 = 0.001f;
    const float inv_s2 = 1.0f / s2;

    // load U
    for (int i = tid; i < NSEG*16; i += 256) {
        int r = i >> 4, c = i & 15;
        su[r][c] = g_gemb[(b*NSEG + r)*16 + c];
    }
    __syncthreads();

    // Gram prefix snapshots every BLKA rows: sbuf[blk*NPK+e] = sum_{l < blk*BLKA} u_l[j]*u_l[k]
    if (tid < NPK) {
        int e = tid, j = 0;
        while ((j+1)*(j+2)/2 <= e) ++j;
        int k = e - j*(j+1)/2;
        float accg = 0.0f;
        for (int blk = 0; blk < NSNAP; ++blk) {
            sbuf[blk*NPK + e] = accg;
            int l0 = blk*BLKA;
#pragma unroll
            for (int l = 0; l < BLKA; ++l)
                accg = fmaf(su[l0+l][j], su[l0+l][k], accg);
        }
    }
    __syncthreads();

    // per-row independent solve (one thread per row, fully register-resident)
    if (tid < NSEG) {
        const int i = tid, blk = i / BLKA;
        float Bm[NPK];
#pragma unroll
        for (int e = 0; e < NPK; ++e) Bm[e] = sbuf[blk*NPK + e];
        for (int l = blk*BLKA; l < i; ++l) {
            float ul[RR];
#pragma unroll
            for (int c = 0; c < RR; ++c) ul[c] = su[l][c];
#pragma unroll
            for (int j = 0; j < RR; ++j)
#pragma unroll
                for (int k = 0; k <= j; ++k)
                    Bm[j*(j+1)/2 + k] = fmaf(ul[j], ul[k], Bm[j*(j+1)/2 + k]);
        }
        // M = I + B/s2 (packed lower)
#pragma unroll
        for (int j = 0; j < RR; ++j)
#pragma unroll
            for (int k = 0; k <= j; ++k) {
                int e = j*(j+1)/2 + k;
                Bm[e] = (j == k) ? fmaf(Bm[e], inv_s2, 1.0f) : Bm[e]*inv_s2;
            }
        // in-place packed Cholesky of M (compile-time indices -> registers)
#pragma unroll
        for (int k = 0; k < RR; ++k) {
            float dk = sqrtf(Bm[k*(k+1)/2 + k]);
            Bm[k*(k+1)/2 + k] = dk;
            float inv = 1.0f / dk;
#pragma unroll
            for (int j = k+1; j < RR; ++j) Bm[j*(j+1)/2 + k] *= inv;
#pragma unroll
            for (int j = k+1; j < RR; ++j) {
                float ljk = Bm[j*(j+1)/2 + k];
#pragma unroll
                for (int l = k+1; l <= j; ++l)
                    Bm[j*(j+1)/2 + l] = fmaf(-ljk, Bm[l*(l+1)/2 + k], Bm[j*(j+1)/2 + l]);
            }
        }
        // forward solve L y = u_i
        float y[RR];
#pragma unroll
        for (int j = 0; j < RR; ++j) {
            float s = su[i][j];
#pragma unroll
            for (int k = 0; k < j; ++k) s = fmaf(-Bm[j*(j+1)/2 + k], y[k], s);
            y[j] = s / Bm[j*(j+1)/2 + j];
        }
        // back solve L^T v = y
        float v[RR];
#pragma unroll
        for (int j = RR-1; j >= 0; --j) {
            float s = y[j];
#pragma unroll
            for (int k = j+1; k < RR; ++k) s = fmaf(-Bm[k*(k+1)/2 + j], v[k], s);
            v[j] = s / Bm[j*(j+1)/2 + j];
        }
        float d = s2;
#pragma unroll
        for (int c = 0; c < RR; ++c) { d = fmaf(su[i][c], v[c], d); sv[i][c] = v[c]; }
        float sd = sqrtf(d);
        ssd[i] = sd;
        sisd[i] = 1.0f / sd;
    }
    __syncthreads();   // phase A done; sbuf (snapshots) now dead

    // ---- phase B: chunked scan over rows, (chunk c, mc column m) per thread ----
    const int m = tid & 15, c = tid >> 4;
    // B1: chunk partial T_c = sum_{j in chunk} w_j v_j
    if (c < NCH) {
        float T[RR];
#pragma unroll
        for (int k = 0; k < RR; ++k) T[k] = 0.0f;
        for (int r = 0; r < CH; ++r) {
            int j = c*CH + r;
            float w = g_eps[(b*NSEG + j)*MCN + m] * sisd[j];
#pragma unroll
            for (int k = 0; k < RR; ++k) T[k] = fmaf(w, sv[j][k], T[k]);
        }
        float* Tout = sbuf + (c*MCN + m)*16;
#pragma unroll
        for (int k = 0; k < RR; ++k) Tout[k] = T[k];
    }
    __syncthreads();
    // B2+B3: offset = sum of earlier chunk partials, then walk own chunk
    if (c < NCH) {
        float S[RR];
#pragma unroll
        for (int k = 0; k < RR; ++k) S[k] = 0.0f;
        for (int c2 = 0; c2 < c; ++c2) {
            const float* Tc = sbuf + (c2*MCN + m)*16;
#pragma unroll
            for (int k = 0; k < RR; ++k) S[k] += Tc[k];
        }
        for (int r = 0; r < CH; ++r) {
            int j = c*CH + r;
            int gi = (b*NSEG + j)*MCN + m;
            float ej = g_eps[gi];
            float dot = 0.0f;
#pragma unroll
            for (int k = 0; k < RR; ++k) dot = fmaf(su[j][k], S[k], dot);
            float z = g_mu[b*NSEG + j] + dot + ssd[j]*ej + g_logi[gi];
            float rr = 1.0f / (1.0f + expf(-z));
            g_hard[gi] = (rr > 0.5f) ? 1.0f : 0.0f;
            float w = ej * sisd[j];
#pragma unroll
            for (int k = 0; k < RR; ++k) S[k] = fmaf(w, sv[j][k], S[k]);
        }
    }
}

// -------------------- kernel 6: gather mask --------------------
__global__ void k_mask(const int* __restrict__ groups, float* __restrict__ mask) {
    const int idx = blockIdx.x * blockDim.x + threadIdx.x;
    const int c = blockIdx.y, b = blockIdx.z;
    const int p = idx >> 2, j = idx & 3;
    const int g = __ldg(&groups[b*HW + p]);
    float4 v = ((const float4*)g_hard)[(b*NSEG + g)*4 + j];
    ((float4*)mask)[ (size_t)((b*CC + c)*HW + p)*4 + j ] = v;
}

// -------------------- launch --------------------
extern "C" void kernel_launch(void* const* d_in, const int* in_sizes, int n_in,
                              void* d_out, int out_size) {
    (void)in_sizes; (void)n_in; (void)out_size;
    const float* x      = (const float*)d_in[0];
    const int*   groups = (const int*)d_in[1];
    const float* Wc     = (const float*)d_in[2];
    const float* bc     = (const float*)d_in[3];
    float* out      = (float*)d_out;
    float* out_mask = out;
    float* out_gp   = out + OFF_GP;
    float* out_pp   = out + OFF_PP;
    float* out_sig  = out + OFF_SIG;

    void* sumsPtr = nullptr;
    cudaGetSymbolAddress(&sumsPtr, g_sums);
    cudaMemsetAsync(sumsPtr, 0, sizeof(float)*BB*NSEG*17);

    uint32_t kg0, kg1, ku0, ku1;
    tf2x32(0u, 42u, 0u, 0u, kg0, kg1);
    tf2x32(0u, 42u, 0u, 1u, ku0, ku1);
    k_rng<<<(NTOT + 255)/256, 256>>>(kg0, kg1, ku0, ku1);

    k_emb_sums<<<dim3(8, BB), 256>>>(x, groups, Wc, bc, out_pp);
    k_means<<<(BB*NSEG + 255)/256, 256>>>(out_gp);
    k_lr<<<BB, 256>>>();
    k_sigma<<<dim3(NSEG, BB), 256>>>(out_sig);
    k_mask<<<dim3(HW*4/256, CC, BB), 256>>>(groups, out_mask);
}

// round 9
// speedup vs baseline: 2.6759x; 1.1090x over previous
#include <cuda_runtime.h>
#include <stdint.h>
#include <math.h>

#define BB 16
#define CC 3
#define HW 50176             // 224*224
#define EMBN 16
#define NSEG 196
#define MCN 16
#define NTOT (BB*NSEG*MCN)   // 50176
#define RR 15                // rank of gemb
#define NPK 120              // packed 15x15 lower triangle
#define BLKA 7               // rows per snapshot block
#define NSNAP (NSEG/BLKA)    // 28
#define CH 14                // scan chunk size
#define NCH (NSEG/CH)        // 14

#define SZ_MASK (BB*CC*HW*MCN)
#define OFF_GP  (SZ_MASK)
#define OFF_PP  (OFF_GP + BB*NSEG)
#define OFF_SIG (OFF_PP + BB*HW)

// -------------------- device scratch --------------------
__device__ float g_sums[BB*NSEG*17];
__device__ float g_gemb[BB*NSEG*16];
__device__ float g_eps[NTOT];
__device__ float g_logi[NTOT];
__device__ float g_hard[NTOT];

// -------------------- threefry2x32 --------------------
__host__ __device__ inline void tf2x32(uint32_t k0, uint32_t k1,
                                       uint32_t x0, uint32_t x1,
                                       uint32_t& o0, uint32_t& o1) {
    uint32_t ks2 = k0 ^ k1 ^ 0x1BD11BDAu;
    x0 += k0; x1 += k1;
#define TF_RND(r) { x0 += x1; x1 = (x1 << (r)) | (x1 >> (32 - (r))); x1 ^= x0; }
    TF_RND(13) TF_RND(15) TF_RND(26) TF_RND(6)
    x0 += k1;  x1 += ks2 + 1u;
    TF_RND(17) TF_RND(29) TF_RND(16) TF_RND(24)
    x0 += ks2; x1 += k0 + 2u;
    TF_RND(13) TF_RND(15) TF_RND(26) TF_RND(6)
    x0 += k0;  x1 += k1 + 3u;
    TF_RND(17) TF_RND(29) TF_RND(16) TF_RND(24)
    x0 += k1;  x1 += ks2 + 4u;
    TF_RND(13) TF_RND(15) TF_RND(26) TF_RND(6)
    x0 += ks2; x1 += k0 + 5u;
#undef TF_RND
    o0 = x0; o1 = x1;
}

__device__ __forceinline__ float erfinv_xla(float x) {
    float w = -log1pf(-x * x);
    float p;
    if (w < 5.0f) {
        w = w - 2.5f;
        p =               2.81022636e-08f;
        p = fmaf(p, w,    3.43273939e-07f);
        p = fmaf(p, w,   -3.5233877e-06f);
        p = fmaf(p, w,   -4.39150654e-06f);
        p = fmaf(p, w,    0.00021858087f);
        p = fmaf(p, w,   -0.00125372503f);
        p = fmaf(p, w,   -0.00417768164f);
        p = fmaf(p, w,    0.246640727f);
        p = fmaf(p, w,    1.50140941f);
    } else {
        w = sqrtf(w) - 3.0f;
        p =              -0.000200214257f;
        p = fmaf(p, w,    0.000100950558f);
        p = fmaf(p, w,    0.00134934322f);
        p = fmaf(p, w,   -0.00367342844f);
        p = fmaf(p, w,    0.00573950773f);
        p = fmaf(p, w,   -0.0076224613f);
        p = fmaf(p, w,    0.00943887047f);
        p = fmaf(p, w,    1.00167406f);
        p = fmaf(p, w,    2.83297682f);
    }
    return p * x;
}

// -------------------- kernel 1: fused rng + conv/segment-sums --------------------
__global__ void k_prep(const float* __restrict__ x, const int* __restrict__ groups,
                       const float* __restrict__ Wc, const float* __restrict__ bc,
                       float* __restrict__ out_pp,
                       uint32_t g0, uint32_t g1, uint32_t u0, uint32_t u1) {
    const int tid = threadIdx.x;
    if (blockIdx.x < 128) {
        // ---- conv + pixel_probs + segment sums ----
        __shared__ float sW[EMBN*CC];
        __shared__ float sB[EMBN];
        __shared__ float acc[NSEG*17];
        const int b  = blockIdx.x >> 3;
        const int q8 = blockIdx.x & 7;
        if (tid < EMBN*CC) sW[tid] = Wc[tid];
        if (tid < EMBN)    sB[tid] = bc[tid];
        for (int i = tid; i < NSEG*17; i += 256) acc[i] = 0.0f;
        __syncthreads();

        const int chunk = HW / 8;
        const int p0 = q8 * chunk;
        const float* xb = x + (size_t)b * CC * HW;
        for (int p = p0 + tid; p < p0 + chunk; p += 256) {
            float x0 = xb[p], x1 = xb[HW + p], x2 = xb[2*HW + p];
            int g = groups[b*HW + p];
            float* a = acc + g * 17;
#pragma unroll
            for (int e = 0; e < EMBN; ++e) {
                float s = fmaf(x2, sW[e*3+2], fmaf(x1, sW[e*3+1], x0 * sW[e*3]));
                float v = s + sB[e];
                if (e == 0) out_pp[b*HW + p] = 1.0f / (1.0f + expf(-v));
                atomicAdd(&a[e], v);
            }
            atomicAdd(&a[16], 1.0f);
        }
        __syncthreads();
        float* gs = g_sums + b * NSEG * 17;
        for (int i = tid; i < NSEG*17; i += 256) atomicAdd(&gs[i], acc[i]);
    } else {
        // ---- RNG: eps + logistic ----
        int i = (blockIdx.x - 128) * 256 + tid;
        if (i >= NTOT) return;
        uint32_t a0, a1;
        tf2x32(g0, g1, 0u, (uint32_t)i, a0, a1);
        {
            uint32_t bits = a0 ^ a1;
            float f  = __uint_as_float((bits >> 9) | 0x3f800000u) - 1.0f;
            const float lo = __uint_as_float(0xBF7FFFFFu);
            const float d  = __fadd_rn(1.0f, -lo);
            float u  = fmaxf(lo, __fadd_rn(__fmul_rn(f, d), lo));
            g_eps[i] = __uint_as_float(0x3FB504F3u) * erfinv_xla(u);
        }
        tf2x32(u0, u1, 0u, (uint32_t)i, a0, a1);
        {
            uint32_t bits = a0 ^ a1;
            float f  = __uint_as_float((bits >> 9) | 0x3f800000u) - 1.0f;
            const float lo = 1e-6f;
            const float hi = (float)(1.0 - 1e-6);
            const float d  = __fadd_rn(hi, -lo);
            float u  = fmaxf(lo, __fadd_rn(__fmul_rn(f, d), lo));
            g_logi[i] = logf(u) - log1pf(-u);
        }
    }
}

// -------------------- kernel 2: means + low-rank Cholesky + logits + hard bits --------------------
// sigma = U U^T + s2*I, U = gemb (196 x 15).
// Snapshot every 7 rows: factor M_blk = I + G_blk/s2 (28 threads).
// Row i: t = M_blk^{-1} u_i via triangular solves vs broadcast L_blk, then
// Sherman-Morrison corrections with published neighbors:
//   v_i = t - sum_{l=base}^{i-1} v_l (v_l . u_i) / (s2 + u_l . v_l)
// d_i = s2 + u_i . v_i ; (L eps)_j = u_j . S_{j-1} + sqrt(d_j) eps_j.
__global__ __launch_bounds__(256) void k_lr(float* __restrict__ out_gp) {
    __shared__ float su[NSEG][17];
    __shared__ float sv[NSEG][17];
    __shared__ float sbuf[3584];   // A: snapshot Grams/factors [28][120]; B: T[14][16][16]
    __shared__ float ssd[NSEG], sisd[NSEG], sden[NSEG], smu[NSEG];
    const int b = blockIdx.x, tid = threadIdx.x;
    const float s2 = 0.001f;
    const float inv_s2 = 1.0f / s2;

    // means (folded k_means)
    if (tid < NSEG) {
        const float* s = g_sums + (b*NSEG + tid)*17;
        float cm = fmaxf(s[16], 1.0f);
        float mu = s[0] / cm;
        smu[tid] = mu;
        out_gp[b*NSEG + tid] = 1.0f / (1.0f + expf(-mu));
        float* ge = g_gemb + (b*NSEG + tid)*16;
#pragma unroll
        for (int c = 0; c < RR; ++c) { float v = s[c+1]/cm; su[tid][c] = v; ge[c] = v; }
        ge[15] = 0.0f;
    }
    __syncthreads();

    // snapshot prefix Grams
    if (tid < NPK) {
        int e = tid, j = 0;
        while ((j+1)*(j+2)/2 <= e) ++j;
        int k = e - j*(j+1)/2;
        float accg = 0.0f;
        for (int blk = 0; blk < NSNAP; ++blk) {
            sbuf[blk*NPK + e] = accg;
            int l0 = blk*BLKA;
#pragma unroll
            for (int l = 0; l < BLKA; ++l)
                accg = fmaf(su[l0+l][j], su[l0+l][k], accg);
        }
    }
    __syncthreads();

    // factor snapshots in place: M = I + G/s2 -> packed Cholesky (28 threads)
    if (tid < NSNAP) {
        float Bm[NPK];
#pragma unroll
        for (int e = 0; e < NPK; ++e) Bm[e] = sbuf[tid*NPK + e];
#pragma unroll
        for (int j = 0; j < RR; ++j)
#pragma unroll
            for (int k = 0; k <= j; ++k) {
                int e = j*(j+1)/2 + k;
                Bm[e] = (j == k) ? fmaf(Bm[e], inv_s2, 1.0f) : Bm[e]*inv_s2;
            }
#pragma unroll
        for (int k = 0; k < RR; ++k) {
            float dk = sqrtf(Bm[k*(k+1)/2 + k]);
            Bm[k*(k+1)/2 + k] = dk;
            float inv = 1.0f / dk;
#pragma unroll
            for (int j = k+1; j < RR; ++j) Bm[j*(j+1)/2 + k] *= inv;
#pragma unroll
            for (int j = k+1; j < RR; ++j) {
                float ljk = Bm[j*(j+1)/2 + k];
#pragma unroll
                for (int l = k+1; l <= j; ++l)
                    Bm[j*(j+1)/2 + l] = fmaf(-ljk, Bm[l*(l+1)/2 + k], Bm[j*(j+1)/2 + l]);
            }
        }
#pragma unroll
        for (int e = 0; e < NPK; ++e) sbuf[tid*NPK + e] = Bm[e];
    }
    __syncthreads();

    // triangular solves against broadcast snapshot factor
    float t[RR];
    int base = 0;
    if (tid < NSEG) {
        int blk = tid / BLKA; base = blk * BLKA;
        const float* Lb = sbuf + blk*NPK;
        float y[RR];
#pragma unroll
        for (int j = 0; j < RR; ++j) {
            float s = su[tid][j];
#pragma unroll
            for (int k = 0; k < j; ++k) s = fmaf(-Lb[j*(j+1)/2 + k], y[k], s);
            y[j] = s / Lb[j*(j+1)/2 + j];
        }
#pragma unroll
        for (int j = RR-1; j >= 0; --j) {
            float s = y[j];
#pragma unroll
            for (int k = j+1; k < RR; ++k) s = fmaf(-Lb[k*(k+1)/2 + j], t[k], s);
            t[j] = s / Lb[j*(j+1)/2 + j];
        }
    }
    // publish rows with offset 0
    if (tid < NSEG && tid == base) {
        float d = s2;
#pragma unroll
        for (int k = 0; k < RR; ++k) { d = fmaf(su[tid][k], t[k], d); sv[tid][k] = t[k]; }
        sden[tid] = d;
    }
    // Sherman-Morrison rounds
    for (int r = 1; r < BLKA; ++r) {
        __syncthreads();
        if (tid < NSEG) {
            int off = tid - base;
            if (off >= r) {
                int l = base + r - 1;
                float cdot = 0.0f;
#pragma unroll
                for (int k = 0; k < RR; ++k) cdot = fmaf(sv[l][k], su[tid][k], cdot);
                float scale = cdot / sden[l];
#pragma unroll
                for (int k = 0; k < RR; ++k) t[k] = fmaf(-scale, sv[l][k], t[k]);
            }
            if (off == r) {
                float d = s2;
#pragma unroll
                for (int k = 0; k < RR; ++k) { d = fmaf(su[tid][k], t[k], d); sv[tid][k] = t[k]; }
                sden[tid] = d;
            }
        }
    }
    __syncthreads();
    if (tid < NSEG) {
        float sd = sqrtf(sden[tid]);
        ssd[tid] = sd;
        sisd[tid] = 1.0f / sd;
    }
    __syncthreads();   // phase A done; sbuf now dead

    // ---- phase B: chunked scan, (chunk c, mc column m) per thread ----
    const int m = tid & 15, c = tid >> 4;
    if (c < NCH) {
        float T[RR];
#pragma unroll
        for (int k = 0; k < RR; ++k) T[k] = 0.0f;
        for (int r = 0; r < CH; ++r) {
            int j = c*CH + r;
            float w = g_eps[(b*NSEG + j)*MCN + m] * sisd[j];
#pragma unroll
            for (int k = 0; k < RR; ++k) T[k] = fmaf(w, sv[j][k], T[k]);
        }
        float* Tout = sbuf + (c*MCN + m)*16;
#pragma unroll
        for (int k = 0; k < RR; ++k) Tout[k] = T[k];
    }
    __syncthreads();
    if (c < NCH) {
        float S[RR];
#pragma unroll
        for (int k = 0; k < RR; ++k) S[k] = 0.0f;
        for (int c2 = 0; c2 < c; ++c2) {
            const float* Tc = sbuf + (c2*MCN + m)*16;
#pragma unroll
            for (int k = 0; k < RR; ++k) S[k] += Tc[k];
        }
        for (int r = 0; r < CH; ++r) {
            int j = c*CH + r;
            int gi = (b*NSEG + j)*MCN + m;
            float ej = g_eps[gi];
            float dot = 0.0f;
#pragma unroll
            for (int k = 0; k < RR; ++k) dot = fmaf(su[j][k], S[k], dot);
            float z = smu[j] + dot + ssd[j]*ej + g_logi[gi];
            float rr = 1.0f / (1.0f + expf(-z));
            g_hard[gi] = (rr > 0.5f) ? 1.0f : 0.0f;
            float w = ej * sisd[j];
#pragma unroll
            for (int k = 0; k < RR; ++k) S[k] = fmaf(w, sv[j][k], S[k]);
        }
    }
}

// -------------------- kernel 3: sigma (tiled) --------------------
__global__ __launch_bounds__(256) void k_sigma(float* __restrict__ out_sig) {
    __shared__ float sgm[NSEG][17];
    const int b = blockIdx.y, q = blockIdx.x;
    const int tid = threadIdx.x;
    for (int ii = tid; ii < NSEG*16; ii += 256) sgm[ii >> 4][ii & 15] = g_gemb[(size_t)b*NSEG*16 + ii];
    __syncthreads();
    const int r0 = q * 49;
    for (int e = tid; e < 49*NSEG; e += 256) {
        int row = r0 + e / NSEG;
        int col = e - (e / NSEG) * NSEG;
        float d = 0.0f;
#pragma unroll
        for (int k = 0; k < RR; ++k) d = fmaf(sgm[row][k], sgm[col][k], d);
        if (row == col) d += 0.001f;
        out_sig[((size_t)b*NSEG + row)*NSEG + col] = d;
    }
}

// -------------------- kernel 4: gather mask (all channels per thread) --------------------
__global__ void k_mask(const int* __restrict__ groups, float* __restrict__ mask) {
    const int idx = blockIdx.x * blockDim.x + threadIdx.x;  // 0 .. HW*4
    const int b = blockIdx.y;
    const int p = idx >> 2, j = idx & 3;
    const int g = __ldg(&groups[b*HW + p]);
    float4 v = ((const float4*)g_hard)[(b*NSEG + g)*4 + j];
#pragma unroll
    for (int c = 0; c < CC; ++c)
        __stcs(((float4*)mask) + ((size_t)(b*CC + c)*HW + p)*4 + j, v);
}

// -------------------- launch --------------------
extern "C" void kernel_launch(void* const* d_in, const int* in_sizes, int n_in,
                              void* d_out, int out_size) {
    (void)in_sizes; (void)n_in; (void)out_size;
    const float* x      = (const float*)d_in[0];
    const int*   groups = (const int*)d_in[1];
    const float* Wc     = (const float*)d_in[2];
    const float* bc     = (const float*)d_in[3];
    float* out      = (float*)d_out;
    float* out_mask = out;
    float* out_gp   = out + OFF_GP;
    float* out_pp   = out + OFF_PP;
    float* out_sig  = out + OFF_SIG;

    void* sumsPtr = nullptr;
    cudaGetSymbolAddress(&sumsPtr, g_sums);
    cudaMemsetAsync(sumsPtr, 0, sizeof(float)*BB*NSEG*17);

    uint32_t kg0, kg1, ku0, ku1;
    tf2x32(0u, 42u, 0u, 0u, kg0, kg1);
    tf2x32(0u, 42u, 0u, 1u, ku0, ku1);

    k_prep<<<128 + (NTOT + 255)/256, 256>>>(x, groups, Wc, bc, out_pp, kg0, kg1, ku0, ku1);
    k_lr<<<BB, 256>>>(out_gp);
    k_sigma<<<dim3(4, BB), 256>>>(out_sig);
    k_mask<<<dim3(HW*4/256, BB), 256>>>(groups, out_mask);
}

// round 10
// speedup vs baseline: 4.2133x; 1.5745x over previous
#include <cuda_runtime.h>
#include <stdint.h>
#include <math.h>

#define BB 16
#define CC 3
#define HW 50176             // 224*224
#define EMBN 16
#define NSEG 196
#define MCN 16
#define NTOT (BB*NSEG*MCN)   // 50176
#define RR 15                // rank of gemb
#define NPK 120              // packed 15x15 lower triangle
#define BLKA 7               // rows per snapshot block
#define NSNAP (NSEG/BLKA)    // 28
#define CH 14                // scan chunk size
#define NCH (NSEG/CH)        // 14
#define NQ 8                 // conv partial slots per batch

#define SZ_MASK (BB*CC*HW*MCN)
#define OFF_GP  (SZ_MASK)
#define OFF_PP  (OFF_GP + BB*NSEG)
#define OFF_SIG (OFF_PP + BB*HW)

// -------------------- device scratch --------------------
__device__ float g_part[BB*NQ*NSEG*4];   // per-CTA partial sums (x0,x1,x2,count)
__device__ float g_gemb[BB*NSEG*16];
__device__ float g_eps[NTOT];
__device__ float g_logi[NTOT];
__device__ float g_hard[NTOT];

// -------------------- threefry2x32 --------------------
__host__ __device__ inline void tf2x32(uint32_t k0, uint32_t k1,
                                       uint32_t x0, uint32_t x1,
                                       uint32_t& o0, uint32_t& o1) {
    uint32_t ks2 = k0 ^ k1 ^ 0x1BD11BDAu;
    x0 += k0; x1 += k1;
#define TF_RND(r) { x0 += x1; x1 = (x1 << (r)) | (x1 >> (32 - (r))); x1 ^= x0; }
    TF_RND(13) TF_RND(15) TF_RND(26) TF_RND(6)
    x0 += k1;  x1 += ks2 + 1u;
    TF_RND(17) TF_RND(29) TF_RND(16) TF_RND(24)
    x0 += ks2; x1 += k0 + 2u;
    TF_RND(13) TF_RND(15) TF_RND(26) TF_RND(6)
    x0 += k0;  x1 += k1 + 3u;
    TF_RND(17) TF_RND(29) TF_RND(16) TF_RND(24)
    x0 += k1;  x1 += ks2 + 4u;
    TF_RND(13) TF_RND(15) TF_RND(26) TF_RND(6)
    x0 += ks2; x1 += k0 + 5u;
#undef TF_RND
    o0 = x0; o1 = x1;
}

__device__ __forceinline__ float erfinv_xla(float x) {
    float w = -log1pf(-x * x);
    float p;
    if (w < 5.0f) {
        w = w - 2.5f;
        p =               2.81022636e-08f;
        p = fmaf(p, w,    3.43273939e-07f);
        p = fmaf(p, w,   -3.5233877e-06f);
        p = fmaf(p, w,   -4.39150654e-06f);
        p = fmaf(p, w,    0.00021858087f);
        p = fmaf(p, w,   -0.00125372503f);
        p = fmaf(p, w,   -0.00417768164f);
        p = fmaf(p, w,    0.246640727f);
        p = fmaf(p, w,    1.50140941f);
    } else {
        w = sqrtf(w) - 3.0f;
        p =              -0.000200214257f;
        p = fmaf(p, w,    0.000100950558f);
        p = fmaf(p, w,    0.00134934322f);
        p = fmaf(p, w,   -0.00367342844f);
        p = fmaf(p, w,    0.00573950773f);
        p = fmaf(p, w,   -0.0076224613f);
        p = fmaf(p, w,    0.00943887047f);
        p = fmaf(p, w,    1.00167406f);
        p = fmaf(p, w,    2.83297682f);
    }
    return p * x;
}

// -------------------- kernel 1: fused rng + conv/x-segment-sums --------------------
// Linearity: segment-mean(emb) = W * segment-mean(x) + b, so only x sums needed.
__global__ void k_prep(const float* __restrict__ x, const int* __restrict__ groups,
                       const float* __restrict__ Wc, const float* __restrict__ bc,
                       float* __restrict__ out_pp,
                       uint32_t g0, uint32_t g1, uint32_t u0, uint32_t u1) {
    const int tid = threadIdx.x;
    if (blockIdx.x < BB*NQ) {
        __shared__ float acc[NSEG*4];
        const int b  = blockIdx.x >> 3;
        const int q8 = blockIdx.x & 7;
        float w0 = Wc[0], w1 = Wc[1], w2 = Wc[2], b0 = bc[0];
        for (int i = tid; i < NSEG*4; i += 256) acc[i] = 0.0f;
        __syncthreads();

        const int chunk = HW / NQ;
        const int p0 = q8 * chunk;
        const float* xb = x + (size_t)b * CC * HW;
        for (int p = p0 + tid; p < p0 + chunk; p += 256) {
            float x0 = xb[p], x1 = xb[HW + p], x2 = xb[2*HW + p];
            int g = groups[b*HW + p];
            float v0 = fmaf(x2, w2, fmaf(x1, w1, x0 * w0)) + b0;
            out_pp[b*HW + p] = 1.0f / (1.0f + expf(-v0));
            float* a = acc + g * 4;
            atomicAdd(&a[0], x0);
            atomicAdd(&a[1], x1);
            atomicAdd(&a[2], x2);
            atomicAdd(&a[3], 1.0f);
        }
        __syncthreads();
        float* gp = g_part + (size_t)(b*NQ + q8) * NSEG * 4;
        for (int i = tid; i < NSEG*4; i += 256) gp[i] = acc[i];
    } else {
        int i = (blockIdx.x - BB*NQ) * 256 + tid;
        if (i >= NTOT) return;
        uint32_t a0, a1;
        tf2x32(g0, g1, 0u, (uint32_t)i, a0, a1);
        {
            uint32_t bits = a0 ^ a1;
            float f  = __uint_as_float((bits >> 9) | 0x3f800000u) - 1.0f;
            const float lo = __uint_as_float(0xBF7FFFFFu);
            const float d  = __fadd_rn(1.0f, -lo);
            float u  = fmaxf(lo, __fadd_rn(__fmul_rn(f, d), lo));
            g_eps[i] = __uint_as_float(0x3FB504F3u) * erfinv_xla(u);
        }
        tf2x32(u0, u1, 0u, (uint32_t)i, a0, a1);
        {
            uint32_t bits = a0 ^ a1;
            float f  = __uint_as_float((bits >> 9) | 0x3f800000u) - 1.0f;
            const float lo = 1e-6f;
            const float hi = (float)(1.0 - 1e-6);
            const float d  = __fadd_rn(hi, -lo);
            float u  = fmaxf(lo, __fadd_rn(__fmul_rn(f, d), lo));
            g_logi[i] = logf(u) - log1pf(-u);
        }
    }
}

// -------------------- kernel 2: means + low-rank Cholesky + logits + hard bits --------------------
// sigma = U U^T + s2*I, U = gemb (196 x 15).
// Snapshot every 7 rows: factor M_blk = I + G_blk/s2 (28 threads).
// Row i: t = M_blk^{-1} u_i via triangular solves vs broadcast L_blk, then
// Sherman-Morrison corrections with published neighbors.
// d_i = s2 + u_i . v_i ; (L eps)_j = u_j . S_{j-1} + sqrt(d_j) eps_j.
__global__ __launch_bounds__(256) void k_lr(const float* __restrict__ Wc,
                                            const float* __restrict__ bc,
                                            float* __restrict__ out_gp) {
    __shared__ float su[NSEG][17];
    __shared__ float sv[NSEG][17];
    __shared__ float sbuf[3584];   // A: snapshot factors [28][120]; B: T[14][16][16]
    __shared__ float ssd[NSEG], sisd[NSEG], sden[NSEG], smu[NSEG];
    __shared__ float sW[EMBN*CC], sB[EMBN];
    const int b = blockIdx.x, tid = threadIdx.x;
    const float s2 = 0.001f;
    const float inv_s2 = 1.0f / s2;

    if (tid < EMBN*CC) sW[tid] = Wc[tid];
    if (tid >= 64 && tid < 64 + EMBN) sB[tid - 64] = bc[tid - 64];
    __syncthreads();

    // means from x-channel partials (linearity)
    if (tid < NSEG) {
        float4 s = make_float4(0.f, 0.f, 0.f, 0.f);
        const float4* gp = (const float4*)g_part + (size_t)b*NQ*NSEG + tid;
#pragma unroll
        for (int q = 0; q < NQ; ++q) {
            float4 v = gp[q*NSEG];
            s.x += v.x; s.y += v.y; s.z += v.z; s.w += v.w;
        }
        float cm = fmaxf(s.w, 1.0f);
        float mx0 = s.x/cm, mx1 = s.y/cm, mx2 = s.z/cm;
        float mu = fmaf(mx2, sW[2], fmaf(mx1, sW[1], mx0*sW[0])) + sB[0];
        smu[tid] = mu;
        out_gp[b*NSEG + tid] = 1.0f / (1.0f + expf(-mu));
        float* ge = g_gemb + (b*NSEG + tid)*16;
#pragma unroll
        for (int c = 0; c < RR; ++c) {
            int e = c + 1;
            float v = fmaf(mx2, sW[e*3+2], fmaf(mx1, sW[e*3+1], mx0*sW[e*3])) + sB[e];
            su[tid][c] = v; ge[c] = v;
        }
        ge[15] = 0.0f;
    }
    __syncthreads();

    // snapshot prefix Grams
    if (tid < NPK) {
        int e = tid, j = 0;
        while ((j+1)*(j+2)/2 <= e) ++j;
        int k = e - j*(j+1)/2;
        float accg = 0.0f;
        for (int blk = 0; blk < NSNAP; ++blk) {
            sbuf[blk*NPK + e] = accg;
            int l0 = blk*BLKA;
#pragma unroll
            for (int l = 0; l < BLKA; ++l)
                accg = fmaf(su[l0+l][j], su[l0+l][k], accg);
        }
    }
    __syncthreads();

    // factor snapshots in place: M = I + G/s2 -> packed Cholesky (28 threads)
    if (tid < NSNAP) {
        float Bm[NPK];
#pragma unroll
        for (int e = 0; e < NPK; ++e) Bm[e] = sbuf[tid*NPK + e];
#pragma unroll
        for (int j = 0; j < RR; ++j)
#pragma unroll
            for (int k = 0; k <= j; ++k) {
                int e = j*(j+1)/2 + k;
                Bm[e] = (j == k) ? fmaf(Bm[e], inv_s2, 1.0f) : Bm[e]*inv_s2;
            }
#pragma unroll
        for (int k = 0; k < RR; ++k) {
            float dk = sqrtf(Bm[k*(k+1)/2 + k]);
            Bm[k*(k+1)/2 + k] = dk;
            float inv = 1.0f / dk;
#pragma unroll
            for (int j = k+1; j < RR; ++j) Bm[j*(j+1)/2 + k] *= inv;
#pragma unroll
            for (int j = k+1; j < RR; ++j) {
                float ljk = Bm[j*(j+1)/2 + k];
#pragma unroll
                for (int l = k+1; l <= j; ++l)
                    Bm[j*(j+1)/2 + l] = fmaf(-ljk, Bm[l*(l+1)/2 + k], Bm[j*(j+1)/2 + l]);
            }
        }
#pragma unroll
        for (int e = 0; e < NPK; ++e) sbuf[tid*NPK + e] = Bm[e];
    }
    __syncthreads();

    // triangular solves against broadcast snapshot factor
    float t[RR];
    int base = 0;
    if (tid < NSEG) {
        int blk = tid / BLKA; base = blk * BLKA;
        const float* Lb = sbuf + blk*NPK;
        float y[RR];
#pragma unroll
        for (int j = 0; j < RR; ++j) {
            float s = su[tid][j];
#pragma unroll
            for (int k = 0; k < j; ++k) s = fmaf(-Lb[j*(j+1)/2 + k], y[k], s);
            y[j] = s / Lb[j*(j+1)/2 + j];
        }
#pragma unroll
        for (int j = RR-1; j >= 0; --j) {
            float s = y[j];
#pragma unroll
            for (int k = j+1; k < RR; ++k) s = fmaf(-Lb[k*(k+1)/2 + j], t[k], s);
            t[j] = s / Lb[j*(j+1)/2 + j];
        }
    }
    if (tid < NSEG && tid == base) {
        float d = s2;
#pragma unroll
        for (int k = 0; k < RR; ++k) { d = fmaf(su[tid][k], t[k], d); sv[tid][k] = t[k]; }
        sden[tid] = d;
    }
    for (int r = 1; r < BLKA; ++r) {
        __syncthreads();
        if (tid < NSEG) {
            int off = tid - base;
            if (off >= r) {
                int l = base + r - 1;
                float cdot = 0.0f;
#pragma unroll
                for (int k = 0; k < RR; ++k) cdot = fmaf(sv[l][k], su[tid][k], cdot);
                float scale = cdot / sden[l];
#pragma unroll
                for (int k = 0; k < RR; ++k) t[k] = fmaf(-scale, sv[l][k], t[k]);
            }
            if (off == r) {
                float d = s2;
#pragma unroll
                for (int k = 0; k < RR; ++k) { d = fmaf(su[tid][k], t[k], d); sv[tid][k] = t[k]; }
                sden[tid] = d;
            }
        }
    }
    __syncthreads();
    if (tid < NSEG) {
        float sd = sqrtf(sden[tid]);
        ssd[tid] = sd;
        sisd[tid] = 1.0f / sd;
    }
    __syncthreads();   // phase A done; sbuf now dead

    // ---- phase B: chunked scan, (chunk c, mc column m) per thread ----
    const int m = tid & 15, c = tid >> 4;
    if (c < NCH) {
        float T[RR];
#pragma unroll
        for (int k = 0; k < RR; ++k) T[k] = 0.0f;
        for (int r = 0; r < CH; ++r) {
            int j = c*CH + r;
            float w = g_eps[(b*NSEG + j)*MCN + m] * sisd[j];
#pragma unroll
            for (int k = 0; k < RR; ++k) T[k] = fmaf(w, sv[j][k], T[k]);
        }
        float* Tout = sbuf + (c*MCN + m)*16;
#pragma unroll
        for (int k = 0; k < RR; ++k) Tout[k] = T[k];
    }
    __syncthreads();
    if (c < NCH) {
        float S[RR];
#pragma unroll
        for (int k = 0; k < RR; ++k) S[k] = 0.0f;
        for (int c2 = 0; c2 < c; ++c2) {
            const float* Tc = sbuf + (c2*MCN + m)*16;
#pragma unroll
            for (int k = 0; k < RR; ++k) S[k] += Tc[k];
        }
        for (int r = 0; r < CH; ++r) {
            int j = c*CH + r;
            int gi = (b*NSEG + j)*MCN + m;
            float ej = g_eps[gi];
            float dot = 0.0f;
#pragma unroll
            for (int k = 0; k < RR; ++k) dot = fmaf(su[j][k], S[k], dot);
            float z = smu[j] + dot + ssd[j]*ej + g_logi[gi];
            float rr = 1.0f / (1.0f + expf(-z));
            g_hard[gi] = (rr > 0.5f) ? 1.0f : 0.0f;
            float w = ej * sisd[j];
#pragma unroll
            for (int k = 0; k < RR; ++k) S[k] = fmaf(w, sv[j][k], S[k]);
        }
    }
}

// -------------------- kernel 3: mask gather + sigma (fused) --------------------
__global__ __launch_bounds__(256) void k_masksig(const int* __restrict__ groups,
                                                 float* __restrict__ mask,
                                                 float* __restrict__ out_sig) {
    const int b = blockIdx.y;
    if (blockIdx.x >= HW*4/256) {
        // ---- sigma tile ----
        __shared__ float sgm[NSEG][17];
        const int q = blockIdx.x - HW*4/256;
        const int tid = threadIdx.x;
        for (int ii = tid; ii < NSEG*16; ii += 256)
            sgm[ii >> 4][ii & 15] = g_gemb[(size_t)b*NSEG*16 + ii];
        __syncthreads();
        const int r0 = q * 49;
        for (int e = tid; e < 49*NSEG; e += 256) {
            int row = r0 + e / NSEG;
            int col = e - (e / NSEG) * NSEG;
            float d = 0.0f;
#pragma unroll
            for (int k = 0; k < RR; ++k) d = fmaf(sgm[row][k], sgm[col][k], d);
            if (row == col) d += 0.001f;
            out_sig[((size_t)b*NSEG + row)*NSEG + col] = d;
        }
        return;
    }
    // ---- mask gather ----
    const int idx = blockIdx.x * 256 + threadIdx.x;
    const int p = idx >> 2, j = idx & 3;
    const int g = __ldg(&groups[b*HW + p]);
    float4 v = ((const float4*)g_hard)[(b*NSEG + g)*4 + j];
#pragma unroll
    for (int c = 0; c < CC; ++c)
        __stcs(((float4*)mask) + ((size_t)(b*CC + c)*HW + p)*4 + j, v);
}

// -------------------- launch --------------------
extern "C" void kernel_launch(void* const* d_in, const int* in_sizes, int n_in,
                              void* d_out, int out_size) {
    (void)in_sizes; (void)n_in; (void)out_size;
    const float* x      = (const float*)d_in[0];
    const int*   groups = (const int*)d_in[1];
    const float* Wc     = (const float*)d_in[2];
    const float* bc     = (const float*)d_in[3];
    float* out      = (float*)d_out;
    float* out_mask = out;
    float* out_gp   = out + OFF_GP;
    float* out_pp   = out + OFF_PP;
    float* out_sig  = out + OFF_SIG;

    uint32_t kg0, kg1, ku0, ku1;
    tf2x32(0u, 42u, 0u, 0u, kg0, kg1);
    tf2x32(0u, 42u, 0u, 1u, ku0, ku1);

    k_prep<<<BB*NQ + (NTOT + 255)/256, 256>>>(x, groups, Wc, bc, out_pp, kg0, kg1, ku0, ku1);
    k_lr<<<BB, 256>>>(Wc, bc, out_gp);
    k_masksig<<<dim3(HW*4/256 + 4, BB), 256>>>(groups, out_mask, out_sig);
}

// round 11
// speedup vs baseline: 4.7468x; 1.1266x over previous
#include <cuda_runtime.h>
#include <stdint.h>
#include <math.h>

#define BB 16
#define CC 3
#define HW 50176             // 224*224
#define EMBN 16
#define NSEG 196
#define MCN 16
#define NTOT (BB*NSEG*MCN)   // 50176
#define RR 15                // rank of gemb
#define NPK 120              // packed 15x15 lower triangle
#define BLKA 7               // rows per snapshot block
#define NSNAP (NSEG/BLKA)    // 28
#define CH 14                // scan chunk size
#define NCH (NSEG/CH)        // 14
#define NQC 16               // conv CTAs per batch

#define SZ_MASK (BB*CC*HW*MCN)
#define OFF_GP  (SZ_MASK)
#define OFF_PP  (OFF_GP + BB*NSEG)
#define OFF_SIG (OFF_PP + BB*HW)

// -------------------- device scratch --------------------
__device__ float4 g_acc[BB*NSEG];        // (sum x0, sum x1, sum x2, count) per (b,seg)
__device__ float g_gemb[BB*NSEG*16];
__device__ float g_eps[NTOT];
__device__ float g_logi[NTOT];
__device__ float g_hard[NTOT];

// -------------------- threefry2x32 --------------------
__host__ __device__ inline void tf2x32(uint32_t k0, uint32_t k1,
                                       uint32_t x0, uint32_t x1,
                                       uint32_t& o0, uint32_t& o1) {
    uint32_t ks2 = k0 ^ k1 ^ 0x1BD11BDAu;
    x0 += k0; x1 += k1;
#define TF_RND(r) { x0 += x1; x1 = (x1 << (r)) | (x1 >> (32 - (r))); x1 ^= x0; }
    TF_RND(13) TF_RND(15) TF_RND(26) TF_RND(6)
    x0 += k1;  x1 += ks2 + 1u;
    TF_RND(17) TF_RND(29) TF_RND(16) TF_RND(24)
    x0 += ks2; x1 += k0 + 2u;
    TF_RND(13) TF_RND(15) TF_RND(26) TF_RND(6)
    x0 += k0;  x1 += k1 + 3u;
    TF_RND(17) TF_RND(29) TF_RND(16) TF_RND(24)
    x0 += k1;  x1 += ks2 + 4u;
    TF_RND(13) TF_RND(15) TF_RND(26) TF_RND(6)
    x0 += ks2; x1 += k0 + 5u;
#undef TF_RND
    o0 = x0; o1 = x1;
}

__device__ __forceinline__ float erfinv_xla(float x) {
    float w = -log1pf(-x * x);
    float p;
    if (w < 5.0f) {
        w = w - 2.5f;
        p =               2.81022636e-08f;
        p = fmaf(p, w,    3.43273939e-07f);
        p = fmaf(p, w,   -3.5233877e-06f);
        p = fmaf(p, w,   -4.39150654e-06f);
        p = fmaf(p, w,    0.00021858087f);
        p = fmaf(p, w,   -0.00125372503f);
        p = fmaf(p, w,   -0.00417768164f);
        p = fmaf(p, w,    0.246640727f);
        p = fmaf(p, w,    1.50140941f);
    } else {
        w = sqrtf(w) - 3.0f;
        p =              -0.000200214257f;
        p = fmaf(p, w,    0.000100950558f);
        p = fmaf(p, w,    0.00134934322f);
        p = fmaf(p, w,   -0.00367342844f);
        p = fmaf(p, w,    0.00573950773f);
        p = fmaf(p, w,   -0.0076224613f);
        p = fmaf(p, w,    0.00943887047f);
        p = fmaf(p, w,    1.00167406f);
        p = fmaf(p, w,    2.83297682f);
    }
    return p * x;
}

// -------------------- kernel 1: fused rng + conv + global-RED segment sums --------------------
__global__ void k_prep(const float* __restrict__ x, const int* __restrict__ groups,
                       const float* __restrict__ Wc, const float* __restrict__ bc,
                       float* __restrict__ out_pp,
                       uint32_t g0, uint32_t g1, uint32_t u0, uint32_t u1) {
    const int tid = threadIdx.x;
    if (blockIdx.x < BB*NQC) {
        const int b = blockIdx.x >> 4;
        const int q = blockIdx.x & 15;
        const float w0 = Wc[0], w1 = Wc[1], w2 = Wc[2], b0 = bc[0];
        const float4* xb = (const float4*)(x + (size_t)b*CC*HW);
        const int4*   gb = (const int4*)(groups + (size_t)b*HW);
        float4* pp = (float4*)(out_pp + (size_t)b*HW);
        float4* acc = g_acc + b*NSEG;
        const int Q4 = HW/4/NQC;           // 784 float4-pixels per CTA
        const int v0 = q * Q4;
        for (int v = v0 + tid; v < v0 + Q4; v += 256) {
            float4 X0 = xb[v], X1 = xb[HW/4 + v], X2 = xb[2*(HW/4) + v];
            int4 G = gb[v];
            float4 o;
            o.x = __fdividef(1.0f, 1.0f + __expf(-(fmaf(X2.x, w2, fmaf(X1.x, w1, X0.x*w0)) + b0)));
            o.y = __fdividef(1.0f, 1.0f + __expf(-(fmaf(X2.y, w2, fmaf(X1.y, w1, X0.y*w0)) + b0)));
            o.z = __fdividef(1.0f, 1.0f + __expf(-(fmaf(X2.z, w2, fmaf(X1.z, w1, X0.z*w0)) + b0)));
            o.w = __fdividef(1.0f, 1.0f + __expf(-(fmaf(X2.w, w2, fmaf(X1.w, w1, X0.w*w0)) + b0)));
            pp[v] = o;
            atomicAdd(&acc[G.x], make_float4(X0.x, X1.x, X2.x, 1.0f));
            atomicAdd(&acc[G.y], make_float4(X0.y, X1.y, X2.y, 1.0f));
            atomicAdd(&acc[G.z], make_float4(X0.z, X1.z, X2.z, 1.0f));
            atomicAdd(&acc[G.w], make_float4(X0.w, X1.w, X2.w, 1.0f));
        }
    } else {
        int i = (blockIdx.x - BB*NQC) * 256 + tid;
        if (i >= NTOT) return;
        uint32_t a0, a1;
        tf2x32(g0, g1, 0u, (uint32_t)i, a0, a1);
        {
            uint32_t bits = a0 ^ a1;
            float f  = __uint_as_float((bits >> 9) | 0x3f800000u) - 1.0f;
            const float lo = __uint_as_float(0xBF7FFFFFu);
            const float d  = __fadd_rn(1.0f, -lo);
            float u  = fmaxf(lo, __fadd_rn(__fmul_rn(f, d), lo));
            g_eps[i] = __uint_as_float(0x3FB504F3u) * erfinv_xla(u);
        }
        tf2x32(u0, u1, 0u, (uint32_t)i, a0, a1);
        {
            uint32_t bits = a0 ^ a1;
            float f  = __uint_as_float((bits >> 9) | 0x3f800000u) - 1.0f;
            const float lo = 1e-6f;
            const float hi = (float)(1.0 - 1e-6);
            const float d  = __fadd_rn(hi, -lo);
            float u  = fmaxf(lo, __fadd_rn(__fmul_rn(f, d), lo));
            g_logi[i] = logf(u) - log1pf(-u);
        }
    }
}

// -------------------- kernel 2: means + low-rank Cholesky + logits + hard bits --------------------
__global__ __launch_bounds__(256) void k_lr(const float* __restrict__ Wc,
                                            const float* __restrict__ bc,
                                            float* __restrict__ out_gp) {
    __shared__ float su[NSEG][17];
    __shared__ float sv[NSEG][17];
    __shared__ float sbuf[3584];   // A: snapshot factors [28][120]; B: T[14][16][16]
    __shared__ float ssd[NSEG], sisd[NSEG], sden[NSEG], smu[NSEG];
    __shared__ float sW[EMBN*CC], sB[EMBN];
    const int b = blockIdx.x, tid = threadIdx.x;
    const float s2 = 0.001f;
    const float inv_s2 = 1.0f / s2;

    if (tid < EMBN*CC) sW[tid] = Wc[tid];
    if (tid >= 64 && tid < 64 + EMBN) sB[tid - 64] = bc[tid - 64];
    __syncthreads();

    // means from x-channel sums (linearity)
    if (tid < NSEG) {
        float4 s = g_acc[b*NSEG + tid];
        float cm = fmaxf(s.w, 1.0f);
        float mx0 = s.x/cm, mx1 = s.y/cm, mx2 = s.z/cm;
        float mu = fmaf(mx2, sW[2], fmaf(mx1, sW[1], mx0*sW[0])) + sB[0];
        smu[tid] = mu;
        out_gp[b*NSEG + tid] = __fdividef(1.0f, 1.0f + __expf(-mu));
        float* ge = g_gemb + (b*NSEG + tid)*16;
#pragma unroll
        for (int c = 0; c < RR; ++c) {
            int e = c + 1;
            float v = fmaf(mx2, sW[e*3+2], fmaf(mx1, sW[e*3+1], mx0*sW[e*3])) + sB[e];
            su[tid][c] = v; ge[c] = v;
        }
        ge[15] = 0.0f;
    }
    __syncthreads();

    // snapshot prefix Grams
    if (tid < NPK) {
        int e = tid, j = 0;
        while ((j+1)*(j+2)/2 <= e) ++j;
        int k = e - j*(j+1)/2;
        float accg = 0.0f;
        for (int blk = 0; blk < NSNAP; ++blk) {
            sbuf[blk*NPK + e] = accg;
            int l0 = blk*BLKA;
#pragma unroll
            for (int l = 0; l < BLKA; ++l)
                accg = fmaf(su[l0+l][j], su[l0+l][k], accg);
        }
    }
    __syncthreads();

    // factor snapshots in place: M = I + G/s2 -> packed Cholesky (28 threads)
    if (tid < NSNAP) {
        float Bm[NPK];
#pragma unroll
        for (int e = 0; e < NPK; ++e) Bm[e] = sbuf[tid*NPK + e];
#pragma unroll
        for (int j = 0; j < RR; ++j)
#pragma unroll
            for (int k = 0; k <= j; ++k) {
                int e = j*(j+1)/2 + k;
                Bm[e] = (j == k) ? fmaf(Bm[e], inv_s2, 1.0f) : Bm[e]*inv_s2;
            }
#pragma unroll
        for (int k = 0; k < RR; ++k) {
            float dk = sqrtf(Bm[k*(k+1)/2 + k]);
            Bm[k*(k+1)/2 + k] = dk;
            float inv = 1.0f / dk;
#pragma unroll
            for (int j = k+1; j < RR; ++j) Bm[j*(j+1)/2 + k] *= inv;
#pragma unroll
            for (int j = k+1; j < RR; ++j) {
                float ljk = Bm[j*(j+1)/2 + k];
#pragma unroll
                for (int l = k+1; l <= j; ++l)
                    Bm[j*(j+1)/2 + l] = fmaf(-ljk, Bm[l*(l+1)/2 + k], Bm[j*(j+1)/2 + l]);
            }
        }
#pragma unroll
        for (int e = 0; e < NPK; ++e) sbuf[tid*NPK + e] = Bm[e];
    }
    __syncthreads();

    // triangular solves against broadcast snapshot factor
    float t[RR];
    int base = 0;
    if (tid < NSEG) {
        int blk = tid / BLKA; base = blk * BLKA;
        const float* Lb = sbuf + blk*NPK;
        float y[RR];
#pragma unroll
        for (int j = 0; j < RR; ++j) {
            float s = su[tid][j];
#pragma unroll
            for (int k = 0; k < j; ++k) s = fmaf(-Lb[j*(j+1)/2 + k], y[k], s);
            y[j] = s / Lb[j*(j+1)/2 + j];
        }
#pragma unroll
        for (int j = RR-1; j >= 0; --j) {
            float s = y[j];
#pragma unroll
            for (int k = j+1; k < RR; ++k) s = fmaf(-Lb[k*(k+1)/2 + j], t[k], s);
            t[j] = s / Lb[j*(j+1)/2 + j];
        }
    }
    if (tid < NSEG && tid == base) {
        float d = s2;
#pragma unroll
        for (int k = 0; k < RR; ++k) { d = fmaf(su[tid][k], t[k], d); sv[tid][k] = t[k]; }
        sden[tid] = d;
    }
    for (int r = 1; r < BLKA; ++r) {
        __syncthreads();
        if (tid < NSEG) {
            int off = tid - base;
            if (off >= r) {
                int l = base + r - 1;
                float cdot = 0.0f;
#pragma unroll
                for (int k = 0; k < RR; ++k) cdot = fmaf(sv[l][k], su[tid][k], cdot);
                float scale = cdot / sden[l];
#pragma unroll
                for (int k = 0; k < RR; ++k) t[k] = fmaf(-scale, sv[l][k], t[k]);
            }
            if (off == r) {
                float d = s2;
#pragma unroll
                for (int k = 0; k < RR; ++k) { d = fmaf(su[tid][k], t[k], d); sv[tid][k] = t[k]; }
                sden[tid] = d;
            }
        }
    }
    __syncthreads();
    if (tid < NSEG) {
        float sd = sqrtf(sden[tid]);
        ssd[tid] = sd;
        sisd[tid] = 1.0f / sd;
    }
    __syncthreads();   // phase A done; sbuf now dead

    // ---- phase B: chunked scan, (chunk c, mc column m) per thread ----
    const int m = tid & 15, c = tid >> 4;
    if (c < NCH) {
        float T[RR];
#pragma unroll
        for (int k = 0; k < RR; ++k) T[k] = 0.0f;
        for (int r = 0; r < CH; ++r) {
            int j = c*CH + r;
            float w = g_eps[(b*NSEG + j)*MCN + m] * sisd[j];
#pragma unroll
            for (int k = 0; k < RR; ++k) T[k] = fmaf(w, sv[j][k], T[k]);
        }
        float* Tout = sbuf + (c*MCN + m)*16;
#pragma unroll
        for (int k = 0; k < RR; ++k) Tout[k] = T[k];
    }
    __syncthreads();
    if (c < NCH) {
        float S[RR];
#pragma unroll
        for (int k = 0; k < RR; ++k) S[k] = 0.0f;
        for (int c2 = 0; c2 < c; ++c2) {
            const float* Tc = sbuf + (c2*MCN + m)*16;
#pragma unroll
            for (int k = 0; k < RR; ++k) S[k] += Tc[k];
        }
        for (int r = 0; r < CH; ++r) {
            int j = c*CH + r;
            int gi = (b*NSEG + j)*MCN + m;
            float ej = g_eps[gi];
            float dot = 0.0f;
#pragma unroll
            for (int k = 0; k < RR; ++k) dot = fmaf(su[j][k], S[k], dot);
            float z = smu[j] + dot + ssd[j]*ej + g_logi[gi];
            g_hard[gi] = (z > 0.0f) ? 1.0f : 0.0f;   // == (sigmoid(z) > 0.5)
            float w = ej * sisd[j];
#pragma unroll
            for (int k = 0; k < RR; ++k) S[k] = fmaf(w, sv[j][k], S[k]);
        }
    }
}

// -------------------- kernel 3: mask gather + sigma (fused) --------------------
__global__ __launch_bounds__(256) void k_masksig(const int* __restrict__ groups,
                                                 float* __restrict__ mask,
                                                 float* __restrict__ out_sig) {
    const int b = blockIdx.y;
    if (blockIdx.x >= HW*4/256) {
        __shared__ float sgm[NSEG][17];
        const int q = blockIdx.x - HW*4/256;
        const int tid = threadIdx.x;
        for (int ii = tid; ii < NSEG*16; ii += 256)
            sgm[ii >> 4][ii & 15] = g_gemb[(size_t)b*NSEG*16 + ii];
        __syncthreads();
        const int r0 = q * 49;
        for (int e = tid; e < 49*NSEG; e += 256) {
            int row = r0 + e / NSEG;
            int col = e - (e / NSEG) * NSEG;
            float d = 0.0f;
#pragma unroll
            for (int k = 0; k < RR; ++k) d = fmaf(sgm[row][k], sgm[col][k], d);
            if (row == col) d += 0.001f;
            out_sig[((size_t)b*NSEG + row)*NSEG + col] = d;
        }
        return;
    }
    const int idx = blockIdx.x * 256 + threadIdx.x;
    const int p = idx >> 2, j = idx & 3;
    const int g = __ldg(&groups[b*HW + p]);
    float4 v = ((const float4*)g_hard)[(b*NSEG + g)*4 + j];
#pragma unroll
    for (int c = 0; c < CC; ++c)
        __stcs(((float4*)mask) + ((size_t)(b*CC + c)*HW + p)*4 + j, v);
}

// -------------------- launch --------------------
extern "C" void kernel_launch(void* const* d_in, const int* in_sizes, int n_in,
                              void* d_out, int out_size) {
    (void)in_sizes; (void)n_in; (void)out_size;
    const float* x      = (const float*)d_in[0];
    const int*   groups = (const int*)d_in[1];
    const float* Wc     = (const float*)d_in[2];
    const float* bc     = (const float*)d_in[3];
    float* out      = (float*)d_out;
    float* out_mask = out;
    float* out_gp   = out + OFF_GP;
    float* out_pp   = out + OFF_PP;
    float* out_sig  = out + OFF_SIG;

    void* accPtr = nullptr;
    cudaGetSymbolAddress(&accPtr, g_acc);
    cudaMemsetAsync(accPtr, 0, sizeof(float4)*BB*NSEG);

    uint32_t kg0, kg1, ku0, ku1;
    tf2x32(0u, 42u, 0u, 0u, kg0, kg1);
    tf2x32(0u, 42u, 0u, 1u, ku0, ku1);

    k_prep<<<BB*NQC + (NTOT + 255)/256, 256>>>(x, groups, Wc, bc, out_pp, kg0, kg1, ku0, ku1);
    k_lr<<<BB, 256>>>(Wc, bc, out_gp);
    k_masksig<<<dim3(HW*4/256 + 4, BB), 256>>>(groups, out_mask, out_sig);
}

// round 13
// speedup vs baseline: 5.1819x; 1.0917x over previous
#include <cuda_runtime.h>
#include <stdint.h>
#include <math.h>

#define BB 16
#define CC 3
#define HW 50176             // 224*224
#define EMBN 16
#define NSEG 196
#define MCN 16
#define NTOT (BB*NSEG*MCN)   // 50176
#define RR 15                // rank of gemb
#define NPK 120              // packed 15x15 lower triangle
#define BLKA 7               // rows per snapshot block
#define NSNAP (NSEG/BLKA)    // 28
#define CH 14                // scan chunk size
#define NCH (NSEG/CH)        // 14
#define NQC 32               // conv CTAs per batch
#define NREP 4               // accumulator replicas

#define SZ_MASK (BB*CC*HW*MCN)
#define OFF_GP  (SZ_MASK)
#define OFF_PP  (OFF_GP + BB*NSEG)
#define OFF_SIG (OFF_PP + BB*HW)

// -------------------- device scratch (zero-initialized at load; k_lr re-zeros) ----
__device__ float4 g_acc4[NREP*BB*NSEG];  // (sum x0, sum x1, sum x2, count), 4 replicas
__device__ float g_gemb[BB*NSEG*16];
__device__ float g_eps[NTOT];
__device__ float g_logi[NTOT];
__device__ float g_hard[NTOT];

// -------------------- threefry2x32 --------------------
__host__ __device__ inline void tf2x32(uint32_t k0, uint32_t k1,
                                       uint32_t x0, uint32_t x1,
                                       uint32_t& o0, uint32_t& o1) {
    uint32_t ks2 = k0 ^ k1 ^ 0x1BD11BDAu;
    x0 += k0; x1 += k1;
#define TF_RND(r) { x0 += x1; x1 = (x1 << (r)) | (x1 >> (32 - (r))); x1 ^= x0; }
    TF_RND(13) TF_RND(15) TF_RND(26) TF_RND(6)
    x0 += k1;  x1 += ks2 + 1u;
    TF_RND(17) TF_RND(29) TF_RND(16) TF_RND(24)
    x0 += ks2; x1 += k0 + 2u;
    TF_RND(13) TF_RND(15) TF_RND(26) TF_RND(6)
    x0 += k0;  x1 += k1 + 3u;
    TF_RND(17) TF_RND(29) TF_RND(16) TF_RND(24)
    x0 += k1;  x1 += ks2 + 4u;
    TF_RND(13) TF_RND(15) TF_RND(26) TF_RND(6)
    x0 += ks2; x1 += k0 + 5u;
#undef TF_RND
    o0 = x0; o1 = x1;
}

__device__ __forceinline__ float erfinv_xla(float x) {
    float w = -log1pf(-x * x);
    float p;
    if (w < 5.0f) {
        w = w - 2.5f;
        p =               2.81022636e-08f;
        p = fmaf(p, w,    3.43273939e-07f);
        p = fmaf(p, w,   -3.5233877e-06f);
        p = fmaf(p, w,   -4.39150654e-06f);
        p = fmaf(p, w,    0.00021858087f);
        p = fmaf(p, w,   -0.00125372503f);
        p = fmaf(p, w,   -0.00417768164f);
        p = fmaf(p, w,    0.246640727f);
        p = fmaf(p, w,    1.50140941f);
    } else {
        w = sqrtf(w) - 3.0f;
        p =              -0.000200214257f;
        p = fmaf(p, w,    0.000100950558f);
        p = fmaf(p, w,    0.00134934322f);
        p = fmaf(p, w,   -0.00367342844f);
        p = fmaf(p, w,    0.00573950773f);
        p = fmaf(p, w,   -0.0076224613f);
        p = fmaf(p, w,    0.00943887047f);
        p = fmaf(p, w,    1.00167406f);
        p = fmaf(p, w,    2.83297682f);
    }
    return p * x;
}

// -------------------- kernel 1: fused rng + conv + replicated global-RED sums -----
__global__ void k_prep(const float* __restrict__ x, const int* __restrict__ groups,
                       const float* __restrict__ Wc, const float* __restrict__ bc,
                       float* __restrict__ out_pp,
                       uint32_t g0, uint32_t g1, uint32_t u0, uint32_t u1) {
    const int tid = threadIdx.x;
    if (blockIdx.x < BB*NQC) {
        const int b = blockIdx.x / NQC;
        const int q = blockIdx.x % NQC;
        const float w0 = Wc[0], w1 = Wc[1], w2 = Wc[2], b0 = bc[0];
        const float4* xb = (const float4*)(x + (size_t)b*CC*HW);
        const int4*   gb = (const int4*)(groups + (size_t)b*HW);
        float4* pp = (float4*)(out_pp + (size_t)b*HW);
        float4* acc = g_acc4 + ((q & (NREP-1))*BB + b)*NSEG;
        const int Q4 = HW/4/NQC;           // 392 float4-pixels per CTA
        const int v0 = q * Q4;
        for (int v = v0 + tid; v < v0 + Q4; v += 256) {
            float4 X0 = xb[v], X1 = xb[HW/4 + v], X2 = xb[2*(HW/4) + v];
            int4 G = gb[v];
            float4 o;
            o.x = __fdividef(1.0f, 1.0f + __expf(-(fmaf(X2.x, w2, fmaf(X1.x, w1, X0.x*w0)) + b0)));
            o.y = __fdividef(1.0f, 1.0f + __expf(-(fmaf(X2.y, w2, fmaf(X1.y, w1, X0.y*w0)) + b0)));
            o.z = __fdividef(1.0f, 1.0f + __expf(-(fmaf(X2.z, w2, fmaf(X1.z, w1, X0.z*w0)) + b0)));
            o.w = __fdividef(1.0f, 1.0f + __expf(-(fmaf(X2.w, w2, fmaf(X1.w, w1, X0.w*w0)) + b0)));
            pp[v] = o;
            atomicAdd(&acc[G.x], make_float4(X0.x, X1.x, X2.x, 1.0f));
            atomicAdd(&acc[G.y], make_float4(X0.y, X1.y, X2.y, 1.0f));
            atomicAdd(&acc[G.z], make_float4(X0.z, X1.z, X2.z, 1.0f));
            atomicAdd(&acc[G.w], make_float4(X0.w, X1.w, X2.w, 1.0f));
        }
    } else {
        int i = (blockIdx.x - BB*NQC) * 256 + tid;
        if (i >= NTOT) return;
        uint32_t a0, a1;
        tf2x32(g0, g1, 0u, (uint32_t)i, a0, a1);
        {
            uint32_t bits = a0 ^ a1;
            float f  = __uint_as_float((bits >> 9) | 0x3f800000u) - 1.0f;
            const float lo = __uint_as_float(0xBF7FFFFFu);
            const float d  = __fadd_rn(1.0f, -lo);
            float u  = fmaxf(lo, __fadd_rn(__fmul_rn(f, d), lo));
            g_eps[i] = __uint_as_float(0x3FB504F3u) * erfinv_xla(u);
        }
        tf2x32(u0, u1, 0u, (uint32_t)i, a0, a1);
        {
            uint32_t bits = a0 ^ a1;
            float f  = __uint_as_float((bits >> 9) | 0x3f800000u) - 1.0f;
            const float lo = 1e-6f;
            const float hi = (float)(1.0 - 1e-6);
            const float d  = __fadd_rn(hi, -lo);
            float u  = fmaxf(lo, __fadd_rn(__fmul_rn(f, d), lo));
            g_logi[i] = logf(u) - log1pf(-u);
        }
    }
}

// -------------------- kernel 2: means + low-rank Cholesky + logits + hard bits ----
__global__ __launch_bounds__(256) void k_lr(const float* __restrict__ Wc,
                                            const float* __restrict__ bc,
                                            float* __restrict__ out_gp) {
    __shared__ float su[NSEG][17];
    __shared__ float sv[NSEG][17];
    __shared__ float sbuf[3584];   // A: snapshot factors [28][120]; B: T[14][16][16]
    __shared__ float ssd[NSEG], sisd[NSEG], sden[NSEG], smu[NSEG];
    __shared__ float sW[EMBN*CC], sB[EMBN];
    const int b = blockIdx.x, tid = threadIdx.x;
    const float s2 = 0.001f;
    const float inv_s2 = 1.0f / s2;

    if (tid < EMBN*CC) sW[tid] = Wc[tid];
    if (tid >= 64 && tid < 64 + EMBN) sB[tid - 64] = bc[tid - 64];
    __syncthreads();

    // means from replicated x-channel sums (linearity)
    if (tid < NSEG) {
        float4 s = make_float4(0.f, 0.f, 0.f, 0.f);
#pragma unroll
        for (int rp = 0; rp < NREP; ++rp) {
            float4 v = g_acc4[(rp*BB + b)*NSEG + tid];
            s.x += v.x; s.y += v.y; s.z += v.z; s.w += v.w;
        }
        float cm = fmaxf(s.w, 1.0f);
        float mx0 = s.x/cm, mx1 = s.y/cm, mx2 = s.z/cm;
        float mu = fmaf(mx2, sW[2], fmaf(mx1, sW[1], mx0*sW[0])) + sB[0];
        smu[tid] = mu;
        out_gp[b*NSEG + tid] = __fdividef(1.0f, 1.0f + __expf(-mu));
        float* ge = g_gemb + (b*NSEG + tid)*16;
#pragma unroll
        for (int c = 0; c < RR; ++c) {
            int e = c + 1;
            float v = fmaf(mx2, sW[e*3+2], fmaf(mx1, sW[e*3+1], mx0*sW[e*3])) + sB[e];
            su[tid][c] = v; ge[c] = v;
        }
        ge[15] = 0.0f;
    }
    // re-zero accumulators for the next graph replay (values already consumed above
    // by this same thread; other threads' entries untouched by this thread's reads)
    __syncthreads();
    {
        float4 z = make_float4(0.f, 0.f, 0.f, 0.f);
        for (int i = tid; i < NREP*NSEG; i += 256)
            g_acc4[((i / NSEG)*BB + b)*NSEG + (i % NSEG)] = z;
    }

    // snapshot prefix Grams
    if (tid < NPK) {
        int e = tid, j = 0;
        while ((j+1)*(j+2)/2 <= e) ++j;
        int k = e - j*(j+1)/2;
        float accg = 0.0f;
        for (int blk = 0; blk < NSNAP; ++blk) {
            sbuf[blk*NPK + e] = accg;
            int l0 = blk*BLKA;
#pragma unroll
            for (int l = 0; l < BLKA; ++l)
                accg = fmaf(su[l0+l][j], su[l0+l][k], accg);
        }
    }
    __syncthreads();

    // factor snapshots in place: M = I + G/s2 -> packed Cholesky (28 threads)
    if (tid < NSNAP) {
        float Bm[NPK];
#pragma unroll
        for (int e = 0; e < NPK; ++e) Bm[e] = sbuf[tid*NPK + e];
#pragma unroll
        for (int j = 0; j < RR; ++j)
#pragma unroll
            for (int k = 0; k <= j; ++k) {
                int e = j*(j+1)/2 + k;
                Bm[e] = (j == k) ? fmaf(Bm[e], inv_s2, 1.0f) : Bm[e]*inv_s2;
            }
#pragma unroll
        for (int k = 0; k < RR; ++k) {
            float dk = sqrtf(Bm[k*(k+1)/2 + k]);
            Bm[k*(k+1)/2 + k] = dk;
            float inv = 1.0f / dk;
#pragma unroll
            for (int j = k+1; j < RR; ++j) Bm[j*(j+1)/2 + k] *= inv;
#pragma unroll
            for (int j = k+1; j < RR; ++j) {
                float ljk = Bm[j*(j+1)/2 + k];
#pragma unroll
                for (int l = k+1; l <= j; ++l)
                    Bm[j*(j+1)/2 + l] = fmaf(-ljk, Bm[l*(l+1)/2 + k], Bm[j*(j+1)/2 + l]);
            }
        }
#pragma unroll
        for (int e = 0; e < NPK; ++e) sbuf[tid*NPK + e] = Bm[e];
    }
    __syncthreads();

    // triangular solves against broadcast snapshot factor
    float t[RR];
    int base = 0;
    if (tid < NSEG) {
        int blk = tid / BLKA; base = blk * BLKA;
        const float* Lb = sbuf + blk*NPK;
        float y[RR];
#pragma unroll
        for (int j = 0; j < RR; ++j) {
            float s = su[tid][j];
#pragma unroll
            for (int k = 0; k < j; ++k) s = fmaf(-Lb[j*(j+1)/2 + k], y[k], s);
            y[j] = s / Lb[j*(j+1)/2 + j];
        }
#pragma unroll
        for (int j = RR-1; j >= 0; --j) {
            float s = y[j];
#pragma unroll
            for (int k = j+1; k < RR; ++k) s = fmaf(-Lb[k*(k+1)/2 + j], t[k], s);
            t[j] = s / Lb[j*(j+1)/2 + j];
        }
    }
    if (tid < NSEG && tid == base) {
        float d = s2;
#pragma unroll
        for (int k = 0; k < RR; ++k) { d = fmaf(su[tid][k], t[k], d); sv[tid][k] = t[k]; }
        sden[tid] = d;
    }
    for (int r = 1; r < BLKA; ++r) {
        __syncthreads();
        if (tid < NSEG) {
            int off = tid - base;
            if (off >= r) {
                int l = base + r - 1;
                float cdot = 0.0f;
#pragma unroll
                for (int k = 0; k < RR; ++k) cdot = fmaf(sv[l][k], su[tid][k], cdot);
                float scale = cdot / sden[l];
#pragma unroll
                for (int k = 0; k < RR; ++k) t[k] = fmaf(-scale, sv[l][k], t[k]);
            }
            if (off == r) {
                float d = s2;
#pragma unroll
                for (int k = 0; k < RR; ++k) { d = fmaf(su[tid][k], t[k], d); sv[tid][k] = t[k]; }
                sden[tid] = d;
            }
        }
    }
    __syncthreads();
    if (tid < NSEG) {
        float sd = sqrtf(sden[tid]);
        ssd[tid] = sd;
        sisd[tid] = 1.0f / sd;
    }
    __syncthreads();   // phase A done; sbuf now dead

    // ---- phase B: chunked scan, (chunk c, mc column m) per thread ----
    const int m = tid & 15, c = tid >> 4;
    if (c < NCH) {
        float T[RR];
#pragma unroll
        for (int k = 0; k < RR; ++k) T[k] = 0.0f;
        for (int r = 0; r < CH; ++r) {
            int j = c*CH + r;
            float w = g_eps[(b*NSEG + j)*MCN + m] * sisd[j];
#pragma unroll
            for (int k = 0; k < RR; ++k) T[k] = fmaf(w, sv[j][k], T[k]);
        }
        float* Tout = sbuf + (c*MCN + m)*16;
#pragma unroll
        for (int k = 0; k < RR; ++k) Tout[k] = T[k];
    }
    __syncthreads();
    if (c < NCH) {
        float S[RR];
#pragma unroll
        for (int k = 0; k < RR; ++k) S[k] = 0.0f;
        for (int c2 = 0; c2 < c; ++c2) {
            const float* Tc = sbuf + (c2*MCN + m)*16;
#pragma unroll
            for (int k = 0; k < RR; ++k) S[k] += Tc[k];
        }
        for (int r = 0; r < CH; ++r) {
            int j = c*CH + r;
            int gi = (b*NSEG + j)*MCN + m;
            float ej = g_eps[gi];
            float dot = 0.0f;
#pragma unroll
            for (int k = 0; k < RR; ++k) dot = fmaf(su[j][k], S[k], dot);
            float z = smu[j] + dot + ssd[j]*ej + g_logi[gi];
            g_hard[gi] = (z > 0.0f) ? 1.0f : 0.0f;   // == (sigmoid(z) > 0.5)
            float w = ej * sisd[j];
#pragma unroll
            for (int k = 0; k < RR; ++k) S[k] = fmaf(w, sv[j][k], S[k]);
        }
    }
}

// -------------------- kernel 3: mask gather + sigma (fused) --------------------
__global__ __launch_bounds__(256) void k_masksig(const int* __restrict__ groups,
                                                 float* __restrict__ mask,
                                                 float* __restrict__ out_sig) {
    const int b = blockIdx.y;
    if (blockIdx.x >= HW*4/256) {
        __shared__ float sgm[NSEG][17];
        const int q = blockIdx.x - HW*4/256;
        const int tid = threadIdx.x;
        for (int ii = tid; ii < NSEG*16; ii += 256)
            sgm[ii >> 4][ii & 15] = g_gemb[(size_t)b*NSEG*16 + ii];
        __syncthreads();
        const int r0 = q * 49;
        for (int e = tid; e < 49*NSEG; e += 256) {
            int row = r0 + e / NSEG;
            int col = e - (e / NSEG) * NSEG;
            float d = 0.0f;
#pragma unroll
            for (int k = 0; k < RR; ++k) d = fmaf(sgm[row][k], sgm[col][k], d);
            if (row == col) d += 0.001f;
            out_sig[((size_t)b*NSEG + row)*NSEG + col] = d;
        }
        return;
    }
    const int idx = blockIdx.x * 256 + threadIdx.x;
    const int p = idx >> 2, j = idx & 3;
    const int g = __ldg(&groups[b*HW + p]);
    float4 v = ((const float4*)g_hard)[(b*NSEG + g)*4 + j];
#pragma unroll
    for (int c = 0; c < CC; ++c)
        __stcs(((float4*)mask) + ((size_t)(b*CC + c)*HW + p)*4 + j, v);
}

// -------------------- launch --------------------
extern "C" void kernel_launch(void* const* d_in, const int* in_sizes, int n_in,
                              void* d_out, int out_size) {
    (void)in_sizes; (void)n_in; (void)out_size;
    const float* x      = (const float*)d_in[0];
    const int*   groups = (const int*)d_in[1];
    const float* Wc     = (const float*)d_in[2];
    const float* bc     = (const float*)d_in[3];
    float* out      = (float*)d_out;
    float* out_mask = out;
    float* out_gp   = out + OFF_GP;
    float* out_pp   = out + OFF_PP;
    float* out_sig  = out + OFF_SIG;

    uint32_t kg0, kg1, ku0, ku1;
    tf2x32(0u, 42u, 0u, 0u, kg0, kg1);
    tf2x32(0u, 42u, 0u, 1u, ku0, ku1);

    k_prep<<<BB*NQC + (NTOT + 255)/256, 256>>>(x, groups, Wc, bc, out_pp, kg0, kg1, ku0, ku1);
    k_lr<<<BB, 256>>>(Wc, bc, out_gp);
    k_masksig<<<dim3(HW*4/256 + 4, BB), 256>>>(groups, out_mask, out_sig);
}